// round 13
// baseline (speedup 1.0000x reference)
#include <cuda_runtime.h>
#include <cuda_fp16.h>
#include <math.h>

// Problem constants
#define BATCH 4
#define SEQ   2048
#define HID   2048
#define NHEAD 16
#define HD    128
#define MTOT  (BATCH*SEQ)        // 8192
#define SCALE 0.08838834764831845f   // 1/sqrt(128)

// Scratch buffers
__device__ __half g_Qh[(size_t)BATCH*NHEAD*SEQ*HD];  // fp16 [bh][s][d] (post-rope)
__device__ __half g_Kh[(size_t)BATCH*NHEAD*SEQ*HD];
__device__ __half g_Vh[(size_t)BATCH*NHEAD*SEQ*HD];  // fp16 [bh][s][d]
__device__ __half g_xh[(size_t)MTOT*HID];            // x fp16; reused as AO fp16
__device__ __half g_wh[4][(size_t)HID*HID];          // weights fp16 (contiguous slabs)
__device__ float  g_tS[(size_t)SEQ*64];              // rope sin table [s][j]
__device__ float  g_tC[(size_t)SEQ*64];              // rope cos table [s][j]

// ---------------------------------------------------------------------------
// PTX helpers
// ---------------------------------------------------------------------------
__device__ __forceinline__ unsigned smem_u32(const void* p) {
    unsigned a;
    asm("{ .reg .u64 t; cvta.to.shared.u64 t, %1; cvt.u32.u64 %0, t; }"
        : "=r"(a) : "l"(p));
    return a;
}

__device__ __forceinline__ void cp16(unsigned dst, const void* src) {
    asm volatile("cp.async.cg.shared.global [%0], [%1], 16;\n"
                 :: "r"(dst), "l"(src) : "memory");
}
#define CP_COMMIT() asm volatile("cp.async.commit_group;\n" ::: "memory")
#define CP_WAIT1()  asm volatile("cp.async.wait_group 1;\n" ::: "memory")
#define CP_WAIT0()  asm volatile("cp.async.wait_group 0;\n" ::: "memory")

__device__ __forceinline__ void ldm_x4(unsigned& r0, unsigned& r1,
                                       unsigned& r2, unsigned& r3, unsigned addr) {
    asm volatile("ldmatrix.sync.aligned.m8n8.x4.shared.b16 {%0,%1,%2,%3}, [%4];"
                 : "=r"(r0), "=r"(r1), "=r"(r2), "=r"(r3) : "r"(addr));
}
__device__ __forceinline__ void ldm_x4_t(unsigned& r0, unsigned& r1,
                                         unsigned& r2, unsigned& r3, unsigned addr) {
    asm volatile("ldmatrix.sync.aligned.m8n8.x4.trans.shared.b16 {%0,%1,%2,%3}, [%4];"
                 : "=r"(r0), "=r"(r1), "=r"(r2), "=r"(r3) : "r"(addr));
}

__device__ __forceinline__ void mma_f16(float (&d)[4], const unsigned (&a)[4],
                                        const unsigned (&b)[2]) {
    asm volatile(
        "mma.sync.aligned.m16n8k16.row.col.f32.f16.f16.f32 "
        "{%0,%1,%2,%3}, {%4,%5,%6,%7}, {%8,%9}, {%0,%1,%2,%3};\n"
        : "+f"(d[0]), "+f"(d[1]), "+f"(d[2]), "+f"(d[3])
        : "r"(a[0]), "r"(a[1]), "r"(a[2]), "r"(a[3]),
          "r"(b[0]), "r"(b[1]));
}

// ---------------------------------------------------------------------------
// Conversions + rope table
// ---------------------------------------------------------------------------
__global__ void cvt_kernel(const float* __restrict__ src,
                           __half* __restrict__ dst, int n4)
{
    const int i = blockIdx.x * blockDim.x + threadIdx.x;
    if (i >= n4) return;
    float4 v = ((const float4*)src)[i];
    __half2* d = (__half2*)&dst[(size_t)4*i];
    d[0] = __floats2half2_rn(v.x, v.y);
    d[1] = __floats2half2_rn(v.z, v.w);
}

__global__ void cvt_w_kernel(const float* __restrict__ w0, const float* __restrict__ w1,
                             const float* __restrict__ w2, const float* __restrict__ w3,
                             __half* __restrict__ dst, int n4)
{
    const int i = blockIdx.x * blockDim.x + threadIdx.x;
    if (i >= n4) return;
    const float* src = (blockIdx.y == 0) ? w0 : (blockIdx.y == 1) ? w1
                     : (blockIdx.y == 2) ? w2 : w3;
    float4 v = ((const float4*)src)[i];
    __half2* d = (__half2*)&dst[(size_t)blockIdx.y * (HID*(size_t)HID) + (size_t)4*i];
    d[0] = __floats2half2_rn(v.x, v.y);
    d[1] = __floats2half2_rn(v.z, v.w);
}

// sin/cos tables, exact same value chain as the original rope kernel
__global__ void rope_tbl_kernel(float* __restrict__ tS, float* __restrict__ tC)
{
    const int idx = blockIdx.x * blockDim.x + threadIdx.x;   // s*64 + j
    const int s = idx >> 6, j = idx & 63;
    const double e = -((double)(2*j) / 128.0) * 9.210340371976184;  // ln(10000)
    const float inv = (float)exp(e);
    const float ang = (float)s * inv;
    float sn, cs;
    sincosf(ang, &sn, &cs);
    tS[idx] = sn;
    tC[idx] = cs;
}

// ---------------------------------------------------------------------------
// fp16 tensor GEMM (NT), C[m,n] = sum_k A[m,k]*W[n,k], fp32 accumulate.
// CTA tile 128x128, warp tile 64x32, 2 CTAs/SM.
// GBK=64 (4 k16 groups/iter), 3-stage cp.async ring: halves barrier count.
// Fragment double-buffer: group g+1 ldm issued before group g's mma block;
// at the last group, prefetch group 0 of stage q+1 (CP_WAIT1 assures residency).
// mode 0 (fused QKV): N=6144; proj = n0>>11:
//   0/1 -> staged rope epilogue, fp16 to qh/kh ([bh][s][d]);  2 -> fp16 to vh
// mode 1: fp32 row-major [M, HID] to fOut.
// ---------------------------------------------------------------------------
#define GBK2 64
#define GROW2 144                        // bytes per smem row (64 halves + 8 pad)
#define TILE2 (128*GROW2)                // 18432
#define STAGE2 (2*TILE2)                 // 36864
#define G_SMEM (3*STAGE2)                // 110592 (>= 128*130*4 = 66560 staging)
#define GNK2 (HID/GBK2)                  // 32
#define STG_STRIDE 130                   // floats per staged row

__global__ __launch_bounds__(256, 2)
void gemm_fp16_kernel(const __half* __restrict__ Ah, const __half* __restrict__ Wh,
                      __half* __restrict__ qOut, __half* __restrict__ kOut,
                      __half* __restrict__ vOut, float* __restrict__ fOut,
                      const float* __restrict__ tblS, const float* __restrict__ tblC,
                      int mode)
{
    extern __shared__ __align__(16) char smem[];
    const unsigned sbase = smem_u32(smem);
    const int tid = threadIdx.x;
    const int warp = tid >> 5, lane = tid & 31;
    const int m0 = blockIdx.y * 128;
    const int n0 = blockIdx.x * 128;
    const int wm = (warp >> 2) * 64;
    const int wn = (warp & 3) * 32;
    const int g = lane >> 2, c = lane & 3;

    float acc[4][4][4];
#pragma unroll
    for (int mt = 0; mt < 4; mt++)
#pragma unroll
        for (int nt = 0; nt < 4; nt++)
#pragma unroll
            for (int e = 0; e < 4; e++) acc[mt][nt][e] = 0.f;

    // Loads: thread -> row = tid>>1, 4 chunks of 16B starting at (tid&1)*64B
    const int lr = tid >> 1;
    const int lc4 = (tid & 1) * 4;               // chunk base (16B units)
    const __half* Ar = Ah + (size_t)(m0 + lr) * HID + lc4 * 8;
    const __half* Wr = Wh + (size_t)(n0 + lr) * HID + lc4 * 8;
    const unsigned sm_off = (unsigned)lr * GROW2 + (unsigned)lc4 * 16;

    auto load_stage = [&](int q) {
        const unsigned s = sbase + (unsigned)(q % 3) * STAGE2;
        const __half* a = Ar + q * GBK2;
        const __half* w = Wr + q * GBK2;
#pragma unroll
        for (int j = 0; j < 4; j++) {
            cp16(s + sm_off + j*16,         a + j*8);
            cp16(s + TILE2 + sm_off + j*16, w + j*8);
        }
    };

    // Fragment smem offsets (within a stage)
    const unsigned aOff = (unsigned)(wm + (lane & 15)) * GROW2
                        + ((unsigned)(lane >> 4) << 4);
    const unsigned bOff = (unsigned)(wn + (lane & 7) + ((lane >> 4) << 3)) * GROW2
                        + (unsigned)((lane >> 3) & 1) * 16;

    auto ldA = [&](unsigned (&a)[4][4], unsigned sa, int k16) {
#pragma unroll
        for (int mt = 0; mt < 4; mt++)
            ldm_x4(a[mt][0], a[mt][1], a[mt][2], a[mt][3],
                   sa + aOff + (unsigned)(16*mt) * GROW2 + (unsigned)k16 * 32);
    };
    auto ldB = [&](unsigned (&b)[4][2], unsigned sb, int k16) {
#pragma unroll
        for (int nt2 = 0; nt2 < 2; nt2++)
            ldm_x4(b[2*nt2][0], b[2*nt2][1], b[2*nt2+1][0], b[2*nt2+1][1],
                   sb + bOff + (unsigned)(16*nt2) * GROW2 + (unsigned)k16 * 32);
    };

    // Prologue: stages 0,1 in flight; wait stage 0; preload group 0
    load_stage(0); CP_COMMIT();
    load_stage(1); CP_COMMIT();
    CP_WAIT1();
    __syncthreads();

    unsigned aF[2][4][4], bF[2][4][2];
    ldA(aF[0], sbase, 0);
    ldB(bF[0], sbase + TILE2, 0);

    for (int q = 0; q < GNK2; q++) {
        __syncthreads();                 // all stage-(q-1) reads done
        if (q + 2 < GNK2) load_stage(q + 2);
        CP_COMMIT();

        const unsigned sa = sbase + (unsigned)(q % 3) * STAGE2;
        const unsigned sb = sa + TILE2;

#pragma unroll
        for (int kg = 0; kg < 4; kg++) {
            const int cur = kg & 1;
            if (kg < 3) {
                ldA(aF[cur ^ 1], sa, kg + 1);
                ldB(bF[cur ^ 1], sb, kg + 1);
            } else if (q + 1 < GNK2) {
                CP_WAIT1();              // stage q+1 resident
                const unsigned sa1 = sbase + (unsigned)((q + 1) % 3) * STAGE2;
                ldA(aF[cur ^ 1], sa1, 0);
                ldB(bF[cur ^ 1], sa1 + TILE2, 0);
            }
#pragma unroll
            for (int mt = 0; mt < 4; mt++)
#pragma unroll
                for (int nt = 0; nt < 4; nt++)
                    mma_f16(acc[mt][nt], aF[cur][mt], bF[cur][nt]);
        }
    }

    // ---------------- Epilogue ----------------
    if (mode == 1) {
#pragma unroll
        for (int mt = 0; mt < 4; mt++)
#pragma unroll
            for (int nt = 0; nt < 4; nt++) {
                const int row = m0 + wm + mt*16 + g;
                const int col = n0 + wn + nt*8 + 2*c;
                *(float2*)(fOut + (size_t)row * HID + col) =
                    make_float2(acc[mt][nt][0], acc[mt][nt][1]);
                *(float2*)(fOut + (size_t)(row + 8) * HID + col) =
                    make_float2(acc[mt][nt][2], acc[mt][nt][3]);
            }
        return;
    }

    const int proj = n0 >> 11;           // 0=Q 1=K 2=V (uniform per CTA)
    const int h = (n0 & 2047) >> 7;

    if (proj == 2) {
        // V: direct fp16 scatter
#pragma unroll
        for (int mt = 0; mt < 4; mt++)
#pragma unroll
            for (int nt = 0; nt < 4; nt++) {
                const int row = m0 + wm + mt*16 + g;
                const int col = n0 + wn + nt*8 + 2*c;
                const int cw = col & 2047;
                const int b = row >> 11;
                const int s = row & (SEQ-1);
                const int d = cw & (HD-1);
                __half* dst = vOut + (((size_t)(b*NHEAD + h))*SEQ + s)*HD + d;
                *(__half2*)dst = __floats2half2_rn(acc[mt][nt][0], acc[mt][nt][1]);
                *(__half2*)(dst + (size_t)8*HD) =
                    __floats2half2_rn(acc[mt][nt][2], acc[mt][nt][3]);
            }
        return;
    }

    // Q/K: stage fp32 tile in smem, apply rope from tables, write fp16
    __syncthreads();                     // ring smem reads all done
    float* st = (float*)smem;            // 128 x STG_STRIDE
#pragma unroll
    for (int mt = 0; mt < 4; mt++)
#pragma unroll
        for (int nt = 0; nt < 4; nt++) {
            const int r = wm + mt*16 + g;
            const int col = wn + nt*8 + 2*c;
            *(float2*)&st[r*STG_STRIDE + col] =
                make_float2(acc[mt][nt][0], acc[mt][nt][1]);
            *(float2*)&st[(r + 8)*STG_STRIDE + col] =
                make_float2(acc[mt][nt][2], acc[mt][nt][3]);
        }
    __syncthreads();

    __half* outh = proj ? kOut : qOut;
    const int j = 2 * lane;              // j, j+1 (0..63)
#pragma unroll 4
    for (int it = 0; it < 16; it++) {
        const int r = warp * 16 + it;
        const int row = m0 + r;
        const int b = row >> 11;
        const int s = row & (SEQ-1);
        float2 sn2 = *(const float2*)&tblS[s*64 + j];
        float2 cs2 = *(const float2*)&tblC[s*64 + j];
        float q1a = st[r*STG_STRIDE + j],      q1b = st[r*STG_STRIDE + j + 1];
        float q2a = st[r*STG_STRIDE + j + 64], q2b = st[r*STG_STRIDE + j + 65];
        __half2 lo = __floats2half2_rn(q1a*sn2.x - q2a*cs2.x, q1b*sn2.y - q2b*cs2.y);
        __half2 hi = __floats2half2_rn(q1a*cs2.x + q2a*sn2.x, q1b*cs2.y + q2b*sn2.y);
        __half* dst = outh + (((size_t)(b*NHEAD + h))*SEQ + s)*HD;
        *(__half2*)&dst[j]      = lo;
        *(__half2*)&dst[j + 64] = hi;
    }
}

// ---------------------------------------------------------------------------
// Causal flash attention, fp16 mma + cp.async double-buffered K/V.
// BR=128, BC=64, 256 threads = 8 warps; warp w owns rows 16w..16w+15.
// blockIdx.x reversed so the longest (diagonal-heavy) CTAs launch first.
// (Round-12 version, verbatim.)
// ---------------------------------------------------------------------------
#define ABR 128
#define ABC 64
#define AQSTR 136                       // halves; 272B row stride (16B-aligned)
#define APSTR 72
#define SQ_BYTES (ABR*AQSTR*2)          // 34816
#define SK_BYTES (ABC*AQSTR*2)          // 17408
#define KV_STAGE (2*SK_BYTES)           // 34816
#define ATTN_SMEM (SQ_BYTES + 2*KV_STAGE)   // 104448

__global__ __launch_bounds__(256, 1)
void attn_f16_kernel(const __half* __restrict__ Qh, const __half* __restrict__ Kh,
                     const __half* __restrict__ Vh, __half* __restrict__ out)
{
    extern __shared__ __align__(16) char smem[];
    __half* sP = (__half*)smem;                  // aliases dead sQ
    const unsigned uQ = smem_u32(smem);
    const unsigned uKV = uQ + SQ_BYTES;
    const unsigned uP = uQ;

    const int bh = blockIdx.y;
    const int q0 = ((int)gridDim.x - 1 - (int)blockIdx.x) * ABR;   // longest first
    const int tid = threadIdx.x;
    const int warp = tid >> 5, lane = tid & 31;
    const int g = lane >> 2, c = lane & 3;
    const int wm = warp * 16;

    const __half* Qb = Qh + (size_t)bh * SEQ * HD;
    const __half* Kb = Kh + (size_t)bh * SEQ * HD;
    const __half* Vb = Vh + (size_t)bh * SEQ * HD;

    auto load_kv = [&](int kt, int stage) {
        const int k0 = kt * ABC;
        const unsigned s = uKV + stage * KV_STAGE;
#pragma unroll
        for (int i = 0; i < 4; i++) {
            const int idx = tid + 256*i;         // 0..1023
            const int r = idx >> 4, ch = idx & 15;
            const unsigned so = (unsigned)r * (AQSTR*2) + (unsigned)ch * 16;
            cp16(s + so,            Kb + (size_t)(k0 + r)*HD + ch*8);
            cp16(s + SK_BYTES + so, Vb + (size_t)(k0 + r)*HD + ch*8);
        }
    };

    // Prologue: async Q tile, then KV tile 0
#pragma unroll
    for (int i = 0; i < 8; i++) {
        const int idx = tid + 256*i;             // 0..2047
        const int r = idx >> 4, ch = idx & 15;
        cp16(uQ + (unsigned)r*(AQSTR*2) + (unsigned)ch*16,
             Qb + (size_t)(q0 + r)*HD + ch*8);
    }
    CP_COMMIT();
    load_kv(0, 0);
    CP_COMMIT();
    CP_WAIT1();                 // Q group complete
    __syncthreads();

    // Hoist Q fragments; sQ is dead afterwards
    unsigned qa[8][4];
#pragma unroll
    for (int k16 = 0; k16 < 8; k16++) {
        const unsigned addr = uQ + (unsigned)(wm + (lane & 15)) * (AQSTR*2)
                            + (unsigned)k16 * 32 + ((unsigned)(lane >> 4) << 4);
        ldm_x4(qa[k16][0], qa[k16][1], qa[k16][2], qa[k16][3], addr);
    }

    float m_r[2] = { -1e30f, -1e30f };
    float l_r[2] = { 0.f, 0.f };
    float acco[16][4];
#pragma unroll
    for (int nt = 0; nt < 16; nt++)
#pragma unroll
        for (int e = 0; e < 4; e++) acco[nt][e] = 0.f;

    const int qi0 = q0 + wm + g;
    const int qi1 = qi0 + 8;
    const int ktmax = q0/ABC + 1;

    for (int kt = 0; kt <= ktmax; kt++) {
        const int k0 = kt * ABC;
        CP_WAIT0();             // tile kt resident
        __syncthreads();        // ...and all threads done reading stage (kt+1)&1
        if (kt + 1 <= ktmax) load_kv(kt + 1, (kt + 1) & 1);
        CP_COMMIT();

        const unsigned uK = uKV + (kt & 1) * KV_STAGE;
        const unsigned uV = uK + SK_BYTES;

        if (k0 > q0 + wm + 15) continue;   // warp tile fully masked

        // ---- S = Q K^T ----
        float accs[8][4];
#pragma unroll
        for (int nt = 0; nt < 8; nt++)
#pragma unroll
            for (int e = 0; e < 4; e++) accs[nt][e] = 0.f;

#pragma unroll
        for (int k16 = 0; k16 < 8; k16++) {
            unsigned b[8][2];
#pragma unroll
            for (int nt2 = 0; nt2 < 4; nt2++) {
                const unsigned addr = uK
                    + (unsigned)(16*nt2 + (lane & 7) + ((lane >> 4) << 3)) * (AQSTR*2)
                    + (unsigned)k16 * 32 + (unsigned)((lane >> 3) & 1) * 16;
                ldm_x4(b[2*nt2][0], b[2*nt2][1], b[2*nt2+1][0], b[2*nt2+1][1], addr);
            }
#pragma unroll
            for (int nt = 0; nt < 8; nt++)
                mma_f16(accs[nt], qa[k16], b[nt]);
        }

        // ---- scale + causal mask + row max ----
        float mx0 = m_r[0], mx1 = m_r[1];
#pragma unroll
        for (int nt = 0; nt < 8; nt++) {
            const int colb = k0 + 8*nt + 2*c;
            float v0 = accs[nt][0] * SCALE; if (colb     > qi0) v0 = -1e30f;
            float v1 = accs[nt][1] * SCALE; if (colb + 1 > qi0) v1 = -1e30f;
            float v2 = accs[nt][2] * SCALE; if (colb     > qi1) v2 = -1e30f;
            float v3 = accs[nt][3] * SCALE; if (colb + 1 > qi1) v3 = -1e30f;
            accs[nt][0] = v0; accs[nt][1] = v1; accs[nt][2] = v2; accs[nt][3] = v3;
            mx0 = fmaxf(mx0, fmaxf(v0, v1));
            mx1 = fmaxf(mx1, fmaxf(v2, v3));
        }
        mx0 = fmaxf(mx0, __shfl_xor_sync(0xffffffffu, mx0, 1));
        mx0 = fmaxf(mx0, __shfl_xor_sync(0xffffffffu, mx0, 2));
        mx1 = fmaxf(mx1, __shfl_xor_sync(0xffffffffu, mx1, 1));
        mx1 = fmaxf(mx1, __shfl_xor_sync(0xffffffffu, mx1, 2));

        const float alpha0 = __expf(m_r[0] - mx0);
        const float alpha1 = __expf(m_r[1] - mx1);
        m_r[0] = mx0; m_r[1] = mx1;

        // ---- exp; round P to fp16; l sums the ROUNDED p ----
        float ls0 = 0.f, ls1 = 0.f;
#pragma unroll
        for (int nt = 0; nt < 8; nt++) {
            __half2 p01 = __floats2half2_rn(__expf(accs[nt][0] - mx0),
                                            __expf(accs[nt][1] - mx0));
            __half2 p23 = __floats2half2_rn(__expf(accs[nt][2] - mx1),
                                            __expf(accs[nt][3] - mx1));
            float2 f01 = __half22float2(p01);
            float2 f23 = __half22float2(p23);
            ls0 += f01.x + f01.y;
            ls1 += f23.x + f23.y;
            *(__half2*)&sP[(wm + g    )*APSTR + 8*nt + 2*c] = p01;
            *(__half2*)&sP[(wm + g + 8)*APSTR + 8*nt + 2*c] = p23;
        }
        ls0 += __shfl_xor_sync(0xffffffffu, ls0, 1);
        ls0 += __shfl_xor_sync(0xffffffffu, ls0, 2);
        ls1 += __shfl_xor_sync(0xffffffffu, ls1, 1);
        ls1 += __shfl_xor_sync(0xffffffffu, ls1, 2);
        l_r[0] = l_r[0] * alpha0 + ls0;
        l_r[1] = l_r[1] * alpha1 + ls1;

#pragma unroll
        for (int nt = 0; nt < 16; nt++) {
            acco[nt][0] *= alpha0; acco[nt][1] *= alpha0;
            acco[nt][2] *= alpha1; acco[nt][3] *= alpha1;
        }
        __syncwarp();   // sP rows are warp-private

        // ---- O += P V ----
#pragma unroll
        for (int k16 = 0; k16 < 4; k16++) {
            unsigned a[4];
            {
                const unsigned addr = uP + (unsigned)(wm + (lane & 15)) * (APSTR*2)
                                    + (unsigned)k16 * 32 + ((unsigned)(lane >> 4) << 4);
                ldm_x4(a[0], a[1], a[2], a[3], addr);
            }
#pragma unroll
            for (int nt2 = 0; nt2 < 8; nt2++) {
                unsigned b[2][2];
                const unsigned addr = uV
                    + (unsigned)(k16*16 + (lane & 7) + (((lane >> 3) & 1) << 3)) * (AQSTR*2)
                    + (unsigned)(2*nt2 + (lane >> 4)) * 16;
                ldm_x4_t(b[0][0], b[0][1], b[1][0], b[1][1], addr);
                mma_f16(acco[2*nt2],     a, b[0]);
                mma_f16(acco[2*nt2 + 1], a, b[1]);
            }
        }
    }

    // Epilogue: normalize, write fp16 [B*S, H]
    const int b = bh >> 4;
    const int h = bh & 15;
    const float inv0 = 1.f / l_r[0];
    const float inv1 = 1.f / l_r[1];
    __half* base0 = out + ((size_t)(b*SEQ + q0 + wm + g    ))*HID + h*HD;
    __half* base1 = out + ((size_t)(b*SEQ + q0 + wm + g + 8))*HID + h*HD;
#pragma unroll
    for (int nt = 0; nt < 16; nt++) {
        *(__half2*)&base0[8*nt + 2*c] = __floats2half2_rn(acco[nt][0]*inv0, acco[nt][1]*inv0);
        *(__half2*)&base1[8*nt + 2*c] = __floats2half2_rn(acco[nt][2]*inv1, acco[nt][3]*inv1);
    }
}

// ---------------------------------------------------------------------------
// Launch
// ---------------------------------------------------------------------------
extern "C" void kernel_launch(void* const* d_in, const int* in_sizes, int n_in,
                              void* d_out, int out_size)
{
    const float* x  = (const float*)d_in[0];

    __half *qh, *kh, *vh, *xh, *wh;
    float *tS, *tC;
    cudaGetSymbolAddress((void**)&qh, g_Qh);
    cudaGetSymbolAddress((void**)&kh, g_Kh);
    cudaGetSymbolAddress((void**)&vh, g_Vh);
    cudaGetSymbolAddress((void**)&xh, g_xh);
    cudaGetSymbolAddress((void**)&wh, g_wh);
    cudaGetSymbolAddress((void**)&tS, g_tS);
    cudaGetSymbolAddress((void**)&tC, g_tC);

    const int nx4 = MTOT*HID/4;
    const int nw4 = HID*HID/4;
    const size_t wstride = (size_t)HID*HID;

    cvt_kernel<<<nx4/256, 256>>>(x, xh, nx4);
    cvt_w_kernel<<<dim3(nw4/256, 4), 256>>>((const float*)d_in[1], (const float*)d_in[2],
                                            (const float*)d_in[3], (const float*)d_in[4],
                                            wh, nw4);
    rope_tbl_kernel<<<SEQ*64/256, 256>>>(tS, tC);

    cudaFuncSetAttribute(gemm_fp16_kernel, cudaFuncAttributeMaxDynamicSharedMemorySize,
                         G_SMEM);

    // Fused QKV projection + rope epilogue: writes qh/kh/vh fp16 directly
    gemm_fp16_kernel<<<dim3(3*HID/128, MTOT/128), 256, G_SMEM>>>(
        xh, wh, qh, kh, vh, nullptr, tS, tC, 0);

    cudaFuncSetAttribute(attn_f16_kernel, cudaFuncAttributeMaxDynamicSharedMemorySize,
                         ATTN_SMEM);
    // attn writes fp16 output into xh (x no longer needed)
    attn_f16_kernel<<<dim3(SEQ/ABR, BATCH*NHEAD), 256, ATTN_SMEM>>>(qh, kh, vh, xh);

    // O projection (fp32 row-major to d_out)
    gemm_fp16_kernel<<<dim3(HID/128, MTOT/128), 256, G_SMEM>>>(
        xh, wh + 3*wstride, nullptr, nullptr, nullptr, (float*)d_out,
        nullptr, nullptr, 1);
}

// round 14
// speedup vs baseline: 1.1321x; 1.1321x over previous
#include <cuda_runtime.h>
#include <cuda_fp16.h>
#include <math.h>

// Problem constants
#define BATCH 4
#define SEQ   2048
#define HID   2048
#define NHEAD 16
#define HD    128
#define MTOT  (BATCH*SEQ)        // 8192
#define SCALE 0.08838834764831845f   // 1/sqrt(128)

// Scratch buffers
__device__ __half g_Qh[(size_t)BATCH*NHEAD*SEQ*HD];  // fp16 [bh][s][d] (post-rope)
__device__ __half g_Kh[(size_t)BATCH*NHEAD*SEQ*HD];
__device__ __half g_Vh[(size_t)BATCH*NHEAD*SEQ*HD];  // fp16 [bh][s][d]
__device__ __half g_xh[(size_t)MTOT*HID];            // x fp16; reused as AO fp16
__device__ __half g_wh[4][(size_t)HID*HID];          // weights fp16 (contiguous slabs)
__device__ float  g_tS[(size_t)SEQ*64];              // rope sin table [s][j]
__device__ float  g_tC[(size_t)SEQ*64];              // rope cos table [s][j]

// ---------------------------------------------------------------------------
// PTX helpers
// ---------------------------------------------------------------------------
__device__ __forceinline__ unsigned smem_u32(const void* p) {
    unsigned a;
    asm("{ .reg .u64 t; cvta.to.shared.u64 t, %1; cvt.u32.u64 %0, t; }"
        : "=r"(a) : "l"(p));
    return a;
}

__device__ __forceinline__ void cp16(unsigned dst, const void* src) {
    asm volatile("cp.async.cg.shared.global [%0], [%1], 16;\n"
                 :: "r"(dst), "l"(src) : "memory");
}
#define CP_COMMIT() asm volatile("cp.async.commit_group;\n" ::: "memory")
#define CP_WAIT2()  asm volatile("cp.async.wait_group 2;\n" ::: "memory")
#define CP_WAIT1()  asm volatile("cp.async.wait_group 1;\n" ::: "memory")
#define CP_WAIT0()  asm volatile("cp.async.wait_group 0;\n" ::: "memory")

__device__ __forceinline__ void ldm_x4(unsigned& r0, unsigned& r1,
                                       unsigned& r2, unsigned& r3, unsigned addr) {
    asm volatile("ldmatrix.sync.aligned.m8n8.x4.shared.b16 {%0,%1,%2,%3}, [%4];"
                 : "=r"(r0), "=r"(r1), "=r"(r2), "=r"(r3) : "r"(addr));
}
__device__ __forceinline__ void ldm_x4_t(unsigned& r0, unsigned& r1,
                                         unsigned& r2, unsigned& r3, unsigned addr) {
    asm volatile("ldmatrix.sync.aligned.m8n8.x4.trans.shared.b16 {%0,%1,%2,%3}, [%4];"
                 : "=r"(r0), "=r"(r1), "=r"(r2), "=r"(r3) : "r"(addr));
}

__device__ __forceinline__ void mma_f16(float (&d)[4], const unsigned (&a)[4],
                                        const unsigned (&b)[2]) {
    asm volatile(
        "mma.sync.aligned.m16n8k16.row.col.f32.f16.f16.f32 "
        "{%0,%1,%2,%3}, {%4,%5,%6,%7}, {%8,%9}, {%0,%1,%2,%3};\n"
        : "+f"(d[0]), "+f"(d[1]), "+f"(d[2]), "+f"(d[3])
        : "r"(a[0]), "r"(a[1]), "r"(a[2]), "r"(a[3]),
          "r"(b[0]), "r"(b[1]));
}

// ---------------------------------------------------------------------------
// Conversions + rope table
// ---------------------------------------------------------------------------
__global__ void cvt_kernel(const float* __restrict__ src,
                           __half* __restrict__ dst, int n4)
{
    const int i = blockIdx.x * blockDim.x + threadIdx.x;
    if (i >= n4) return;
    float4 v = ((const float4*)src)[i];
    __half2* d = (__half2*)&dst[(size_t)4*i];
    d[0] = __floats2half2_rn(v.x, v.y);
    d[1] = __floats2half2_rn(v.z, v.w);
}

__global__ void cvt_w_kernel(const float* __restrict__ w0, const float* __restrict__ w1,
                             const float* __restrict__ w2, const float* __restrict__ w3,
                             __half* __restrict__ dst, int n4)
{
    const int i = blockIdx.x * blockDim.x + threadIdx.x;
    if (i >= n4) return;
    const float* src = (blockIdx.y == 0) ? w0 : (blockIdx.y == 1) ? w1
                     : (blockIdx.y == 2) ? w2 : w3;
    float4 v = ((const float4*)src)[i];
    __half2* d = (__half2*)&dst[(size_t)blockIdx.y * (HID*(size_t)HID) + (size_t)4*i];
    d[0] = __floats2half2_rn(v.x, v.y);
    d[1] = __floats2half2_rn(v.z, v.w);
}

// sin/cos tables, exact same value chain as the original rope kernel
__global__ void rope_tbl_kernel(float* __restrict__ tS, float* __restrict__ tC)
{
    const int idx = blockIdx.x * blockDim.x + threadIdx.x;   // s*64 + j
    const int s = idx >> 6, j = idx & 63;
    const double e = -((double)(2*j) / 128.0) * 9.210340371976184;  // ln(10000)
    const float inv = (float)exp(e);
    const float ang = (float)s * inv;
    float sn, cs;
    sincosf(ang, &sn, &cs);
    tS[idx] = sn;
    tC[idx] = cs;
}

// ---------------------------------------------------------------------------
// fp16 tensor GEMM (NT) — ROUND-10 CONFIG, FROZEN.
// CTA tile 128x128, warp tile 64x32, GBK=32, 4-stage ring, 2 CTAs/SM.
// Fragment-level software pipeline within the iteration.
// mode 0 (fused QKV): N=6144; proj = n0>>11:
//   0/1 -> staged rope epilogue, fp16 to qh/kh ([bh][s][d]);  2 -> fp16 to vh
// mode 1: fp32 row-major [M, HID] to fOut.
// ---------------------------------------------------------------------------
#define GBK 32
#define GROWB 80                         // bytes per smem row (40 halves)
#define GTILE_B (128*GROWB)              // 10240
#define GSTAGE_B (2*GTILE_B)             // 20480
#define G_SMEM (4*GSTAGE_B)              // 81920 (>= 128*130*4 = 66560 staging)
#define GNK (HID/GBK)                    // 64
#define STG_STRIDE 130                   // floats per staged row

__global__ __launch_bounds__(256, 2)
void gemm_fp16_kernel(const __half* __restrict__ Ah, const __half* __restrict__ Wh,
                      __half* __restrict__ qOut, __half* __restrict__ kOut,
                      __half* __restrict__ vOut, float* __restrict__ fOut,
                      const float* __restrict__ tblS, const float* __restrict__ tblC,
                      int mode)
{
    extern __shared__ __align__(16) char smem[];
    const unsigned sbase = smem_u32(smem);
    const int tid = threadIdx.x;
    const int warp = tid >> 5, lane = tid & 31;
    const int m0 = blockIdx.y * 128;
    const int n0 = blockIdx.x * 128;
    const int wm = (warp >> 2) * 64;
    const int wn = (warp & 3) * 32;
    const int g = lane >> 2, c = lane & 3;

    float acc[4][4][4];
#pragma unroll
    for (int mt = 0; mt < 4; mt++)
#pragma unroll
        for (int nt = 0; nt < 4; nt++)
#pragma unroll
            for (int e = 0; e < 4; e++) acc[mt][nt][e] = 0.f;

    const int lrow = tid >> 1;
    const int lofs = (tid & 1) << 4;
    const __half* Ar = Ah + (size_t)(m0 + lrow) * HID + lofs;
    const __half* Wr = Wh + (size_t)(n0 + lrow) * HID + lofs;
    const unsigned sm_off = (unsigned)lrow * GROWB + (unsigned)(tid & 1) * 32;

    auto load_stage = [&](int q) {
        const unsigned s = sbase + (q & 3) * GSTAGE_B;
        const __half* a = Ar + q * GBK;
        const __half* w = Wr + q * GBK;
        cp16(s + sm_off,                a);
        cp16(s + sm_off + 16,           a + 8);
        cp16(s + GTILE_B + sm_off,      w);
        cp16(s + GTILE_B + sm_off + 16, w + 8);
    };

    load_stage(0); CP_COMMIT();
    load_stage(1); CP_COMMIT();
    load_stage(2); CP_COMMIT();

    // Precomputed fragment smem offsets (within a stage)
    const unsigned aRowOff = (unsigned)(wm + (lane & 15)) * GROWB
                           + ((unsigned)(lane >> 4) << 4);
    const unsigned bRowOff = (unsigned)(wn + (lane & 7) + ((lane >> 4) << 3)) * GROWB
                           + (unsigned)((lane >> 3) & 1) * 16;

    for (int q = 0; q < GNK; q++) {
        CP_WAIT2();
        __syncthreads();
        if (q + 3 < GNK) load_stage(q + 3);
        CP_COMMIT();

        const unsigned sa = sbase + (q & 3) * GSTAGE_B;
        const unsigned sb = sa + GTILE_B;

        // ---- load ALL fragments for both k16 steps (12 independent ldm) ----
        unsigned a0[4][4], a1[4][4], b0[4][2], b1[4][2];
#pragma unroll
        for (int mt = 0; mt < 4; mt++) {
            const unsigned base = sa + aRowOff + (unsigned)(16*mt) * GROWB;
            ldm_x4(a0[mt][0], a0[mt][1], a0[mt][2], a0[mt][3], base);
            ldm_x4(a1[mt][0], a1[mt][1], a1[mt][2], a1[mt][3], base + 32);
        }
#pragma unroll
        for (int nt2 = 0; nt2 < 2; nt2++) {
            const unsigned base = sb + bRowOff + (unsigned)(16*nt2) * GROWB;
            ldm_x4(b0[2*nt2][0], b0[2*nt2][1], b0[2*nt2+1][0], b0[2*nt2+1][1], base);
            ldm_x4(b1[2*nt2][0], b1[2*nt2][1], b1[2*nt2+1][0], b1[2*nt2+1][1], base + 32);
        }

        // ---- mma blocks (k16=0 then k16=1) ----
#pragma unroll
        for (int mt = 0; mt < 4; mt++)
#pragma unroll
            for (int nt = 0; nt < 4; nt++)
                mma_f16(acc[mt][nt], a0[mt], b0[nt]);
#pragma unroll
        for (int mt = 0; mt < 4; mt++)
#pragma unroll
            for (int nt = 0; nt < 4; nt++)
                mma_f16(acc[mt][nt], a1[mt], b1[nt]);
    }

    // ---------------- Epilogue ----------------
    if (mode == 1) {
#pragma unroll
        for (int mt = 0; mt < 4; mt++)
#pragma unroll
            for (int nt = 0; nt < 4; nt++) {
                const int row = m0 + wm + mt*16 + g;
                const int col = n0 + wn + nt*8 + 2*c;
                *(float2*)(fOut + (size_t)row * HID + col) =
                    make_float2(acc[mt][nt][0], acc[mt][nt][1]);
                *(float2*)(fOut + (size_t)(row + 8) * HID + col) =
                    make_float2(acc[mt][nt][2], acc[mt][nt][3]);
            }
        return;
    }

    const int proj = n0 >> 11;           // 0=Q 1=K 2=V (uniform per CTA)
    const int h = (n0 & 2047) >> 7;

    if (proj == 2) {
        // V: direct fp16 scatter
#pragma unroll
        for (int mt = 0; mt < 4; mt++)
#pragma unroll
            for (int nt = 0; nt < 4; nt++) {
                const int row = m0 + wm + mt*16 + g;
                const int col = n0 + wn + nt*8 + 2*c;
                const int cw = col & 2047;
                const int b = row >> 11;
                const int s = row & (SEQ-1);
                const int d = cw & (HD-1);
                __half* dst = vOut + (((size_t)(b*NHEAD + h))*SEQ + s)*HD + d;
                *(__half2*)dst = __floats2half2_rn(acc[mt][nt][0], acc[mt][nt][1]);
                *(__half2*)(dst + (size_t)8*HD) =
                    __floats2half2_rn(acc[mt][nt][2], acc[mt][nt][3]);
            }
        return;
    }

    // Q/K: stage fp32 tile in smem, apply rope from tables, write fp16
    __syncthreads();                     // ring smem reads all done
    float* st = (float*)smem;            // 128 x STG_STRIDE
#pragma unroll
    for (int mt = 0; mt < 4; mt++)
#pragma unroll
        for (int nt = 0; nt < 4; nt++) {
            const int r = wm + mt*16 + g;
            const int col = wn + nt*8 + 2*c;
            *(float2*)&st[r*STG_STRIDE + col] =
                make_float2(acc[mt][nt][0], acc[mt][nt][1]);
            *(float2*)&st[(r + 8)*STG_STRIDE + col] =
                make_float2(acc[mt][nt][2], acc[mt][nt][3]);
        }
    __syncthreads();

    __half* outh = proj ? kOut : qOut;
    const int j = 2 * lane;              // j, j+1 (0..63)
#pragma unroll 4
    for (int it = 0; it < 16; it++) {
        const int r = warp * 16 + it;
        const int row = m0 + r;
        const int b = row >> 11;
        const int s = row & (SEQ-1);
        float2 sn2 = *(const float2*)&tblS[s*64 + j];
        float2 cs2 = *(const float2*)&tblC[s*64 + j];
        float q1a = st[r*STG_STRIDE + j],      q1b = st[r*STG_STRIDE + j + 1];
        float q2a = st[r*STG_STRIDE + j + 64], q2b = st[r*STG_STRIDE + j + 65];
        __half2 lo = __floats2half2_rn(q1a*sn2.x - q2a*cs2.x, q1b*sn2.y - q2b*cs2.y);
        __half2 hi = __floats2half2_rn(q1a*cs2.x + q2a*sn2.x, q1b*cs2.y + q2b*sn2.y);
        __half* dst = outh + (((size_t)(b*NHEAD + h))*SEQ + s)*HD;
        *(__half2*)&dst[j]      = lo;
        *(__half2*)&dst[j + 64] = hi;
    }
}

// ---------------------------------------------------------------------------
// Causal flash attention, fp16 mma + 3-stage cp.async KV ring.
// BR=128, BC=64, 256 threads = 8 warps; warp w owns rows 16w..16w+15.
// Per iter: wait_group<=1 (tile kt resident, kt+1 in flight) -> sync ->
//           issue tile kt+2 -> compute kt. Stage (kt+2)%3 was last read
//           at iter kt-1, fenced by this iteration's barrier.
// blockIdx.x reversed so the longest (diagonal-heavy) CTAs launch first.
// ---------------------------------------------------------------------------
#define ABR 128
#define ABC 64
#define AQSTR 136                       // halves; 272B row stride (16B-aligned)
#define APSTR 72
#define SQ_BYTES (ABR*AQSTR*2)          // 34816
#define SK_BYTES (ABC*AQSTR*2)          // 17408
#define KV_STAGE (2*SK_BYTES)           // 34816
#define ATTN_SMEM (SQ_BYTES + 3*KV_STAGE)   // 139264

__global__ __launch_bounds__(256, 1)
void attn_f16_kernel(const __half* __restrict__ Qh, const __half* __restrict__ Kh,
                     const __half* __restrict__ Vh, __half* __restrict__ out)
{
    extern __shared__ __align__(16) char smem[];
    __half* sP = (__half*)smem;                  // aliases dead sQ
    const unsigned uQ = smem_u32(smem);
    const unsigned uKV = uQ + SQ_BYTES;
    const unsigned uP = uQ;

    const int bh = blockIdx.y;
    const int q0 = ((int)gridDim.x - 1 - (int)blockIdx.x) * ABR;   // longest first
    const int tid = threadIdx.x;
    const int warp = tid >> 5, lane = tid & 31;
    const int g = lane >> 2, c = lane & 3;
    const int wm = warp * 16;

    const __half* Qb = Qh + (size_t)bh * SEQ * HD;
    const __half* Kb = Kh + (size_t)bh * SEQ * HD;
    const __half* Vb = Vh + (size_t)bh * SEQ * HD;

    auto load_kv = [&](int kt) {
        const int k0 = kt * ABC;
        const unsigned s = uKV + (unsigned)(kt % 3) * KV_STAGE;
#pragma unroll
        for (int i = 0; i < 4; i++) {
            const int idx = tid + 256*i;         // 0..1023
            const int r = idx >> 4, ch = idx & 15;
            const unsigned so = (unsigned)r * (AQSTR*2) + (unsigned)ch * 16;
            cp16(s + so,            Kb + (size_t)(k0 + r)*HD + ch*8);
            cp16(s + SK_BYTES + so, Vb + (size_t)(k0 + r)*HD + ch*8);
        }
    };

    const int ktmax = q0/ABC + 1;

    // Prologue: async Q tile, then KV tiles 0 and 1
#pragma unroll
    for (int i = 0; i < 8; i++) {
        const int idx = tid + 256*i;             // 0..2047
        const int r = idx >> 4, ch = idx & 15;
        cp16(uQ + (unsigned)r*(AQSTR*2) + (unsigned)ch*16,
             Qb + (size_t)(q0 + r)*HD + ch*8);
    }
    CP_COMMIT();
    load_kv(0);
    CP_COMMIT();
    if (1 <= ktmax) load_kv(1);
    CP_COMMIT();
    CP_WAIT2();                 // Q group complete (kv0, kv1 may be pending)
    __syncthreads();

    // Hoist Q fragments; sQ is dead afterwards
    unsigned qa[8][4];
#pragma unroll
    for (int k16 = 0; k16 < 8; k16++) {
        const unsigned addr = uQ + (unsigned)(wm + (lane & 15)) * (AQSTR*2)
                            + (unsigned)k16 * 32 + ((unsigned)(lane >> 4) << 4);
        ldm_x4(qa[k16][0], qa[k16][1], qa[k16][2], qa[k16][3], addr);
    }

    float m_r[2] = { -1e30f, -1e30f };
    float l_r[2] = { 0.f, 0.f };
    float acco[16][4];
#pragma unroll
    for (int nt = 0; nt < 16; nt++)
#pragma unroll
        for (int e = 0; e < 4; e++) acco[nt][e] = 0.f;

    const int qi0 = q0 + wm + g;
    const int qi1 = qi0 + 8;

    for (int kt = 0; kt <= ktmax; kt++) {
        const int k0 = kt * ABC;
        CP_WAIT1();             // tile kt resident (kt+1 may still be in flight)
        __syncthreads();        // ...and all reads of stage (kt+2)%3 (iter kt-1) done
        if (kt + 2 <= ktmax) load_kv(kt + 2);
        CP_COMMIT();

        const unsigned uK = uKV + (unsigned)(kt % 3) * KV_STAGE;
        const unsigned uV = uK + SK_BYTES;

        if (k0 > q0 + wm + 15) continue;   // warp tile fully masked

        // ---- S = Q K^T ----
        float accs[8][4];
#pragma unroll
        for (int nt = 0; nt < 8; nt++)
#pragma unroll
            for (int e = 0; e < 4; e++) accs[nt][e] = 0.f;

#pragma unroll
        for (int k16 = 0; k16 < 8; k16++) {
            unsigned b[8][2];
#pragma unroll
            for (int nt2 = 0; nt2 < 4; nt2++) {
                const unsigned addr = uK
                    + (unsigned)(16*nt2 + (lane & 7) + ((lane >> 4) << 3)) * (AQSTR*2)
                    + (unsigned)k16 * 32 + (unsigned)((lane >> 3) & 1) * 16;
                ldm_x4(b[2*nt2][0], b[2*nt2][1], b[2*nt2+1][0], b[2*nt2+1][1], addr);
            }
#pragma unroll
            for (int nt = 0; nt < 8; nt++)
                mma_f16(accs[nt], qa[k16], b[nt]);
        }

        // ---- scale + causal mask + row max ----
        float mx0 = m_r[0], mx1 = m_r[1];
#pragma unroll
        for (int nt = 0; nt < 8; nt++) {
            const int colb = k0 + 8*nt + 2*c;
            float v0 = accs[nt][0] * SCALE; if (colb     > qi0) v0 = -1e30f;
            float v1 = accs[nt][1] * SCALE; if (colb + 1 > qi0) v1 = -1e30f;
            float v2 = accs[nt][2] * SCALE; if (colb     > qi1) v2 = -1e30f;
            float v3 = accs[nt][3] * SCALE; if (colb + 1 > qi1) v3 = -1e30f;
            accs[nt][0] = v0; accs[nt][1] = v1; accs[nt][2] = v2; accs[nt][3] = v3;
            mx0 = fmaxf(mx0, fmaxf(v0, v1));
            mx1 = fmaxf(mx1, fmaxf(v2, v3));
        }
        mx0 = fmaxf(mx0, __shfl_xor_sync(0xffffffffu, mx0, 1));
        mx0 = fmaxf(mx0, __shfl_xor_sync(0xffffffffu, mx0, 2));
        mx1 = fmaxf(mx1, __shfl_xor_sync(0xffffffffu, mx1, 1));
        mx1 = fmaxf(mx1, __shfl_xor_sync(0xffffffffu, mx1, 2));

        const float alpha0 = __expf(m_r[0] - mx0);
        const float alpha1 = __expf(m_r[1] - mx1);
        m_r[0] = mx0; m_r[1] = mx1;

        // ---- exp; round P to fp16; l sums the ROUNDED p ----
        float ls0 = 0.f, ls1 = 0.f;
#pragma unroll
        for (int nt = 0; nt < 8; nt++) {
            __half2 p01 = __floats2half2_rn(__expf(accs[nt][0] - mx0),
                                            __expf(accs[nt][1] - mx0));
            __half2 p23 = __floats2half2_rn(__expf(accs[nt][2] - mx1),
                                            __expf(accs[nt][3] - mx1));
            float2 f01 = __half22float2(p01);
            float2 f23 = __half22float2(p23);
            ls0 += f01.x + f01.y;
            ls1 += f23.x + f23.y;
            *(__half2*)&sP[(wm + g    )*APSTR + 8*nt + 2*c] = p01;
            *(__half2*)&sP[(wm + g + 8)*APSTR + 8*nt + 2*c] = p23;
        }
        ls0 += __shfl_xor_sync(0xffffffffu, ls0, 1);
        ls0 += __shfl_xor_sync(0xffffffffu, ls0, 2);
        ls1 += __shfl_xor_sync(0xffffffffu, ls1, 1);
        ls1 += __shfl_xor_sync(0xffffffffu, ls1, 2);
        l_r[0] = l_r[0] * alpha0 + ls0;
        l_r[1] = l_r[1] * alpha1 + ls1;

#pragma unroll
        for (int nt = 0; nt < 16; nt++) {
            acco[nt][0] *= alpha0; acco[nt][1] *= alpha0;
            acco[nt][2] *= alpha1; acco[nt][3] *= alpha1;
        }
        __syncwarp();   // sP rows are warp-private

        // ---- O += P V ----
#pragma unroll
        for (int k16 = 0; k16 < 4; k16++) {
            unsigned a[4];
            {
                const unsigned addr = uP + (unsigned)(wm + (lane & 15)) * (APSTR*2)
                                    + (unsigned)k16 * 32 + ((unsigned)(lane >> 4) << 4);
                ldm_x4(a[0], a[1], a[2], a[3], addr);
            }
#pragma unroll
            for (int nt2 = 0; nt2 < 8; nt2++) {
                unsigned b[2][2];
                const unsigned addr = uV
                    + (unsigned)(k16*16 + (lane & 7) + (((lane >> 3) & 1) << 3)) * (AQSTR*2)
                    + (unsigned)(2*nt2 + (lane >> 4)) * 16;
                ldm_x4_t(b[0][0], b[0][1], b[1][0], b[1][1], addr);
                mma_f16(acco[2*nt2],     a, b[0]);
                mma_f16(acco[2*nt2 + 1], a, b[1]);
            }
        }
    }

    // Epilogue: normalize, write fp16 [B*S, H]
    const int b = bh >> 4;
    const int h = bh & 15;
    const float inv0 = 1.f / l_r[0];
    const float inv1 = 1.f / l_r[1];
    __half* base0 = out + ((size_t)(b*SEQ + q0 + wm + g    ))*HID + h*HD;
    __half* base1 = out + ((size_t)(b*SEQ + q0 + wm + g + 8))*HID + h*HD;
#pragma unroll
    for (int nt = 0; nt < 16; nt++) {
        *(__half2*)&base0[8*nt + 2*c] = __floats2half2_rn(acco[nt][0]*inv0, acco[nt][1]*inv0);
        *(__half2*)&base1[8*nt + 2*c] = __floats2half2_rn(acco[nt][2]*inv1, acco[nt][3]*inv1);
    }
}

// ---------------------------------------------------------------------------
// Launch
// ---------------------------------------------------------------------------
extern "C" void kernel_launch(void* const* d_in, const int* in_sizes, int n_in,
                              void* d_out, int out_size)
{
    const float* x  = (const float*)d_in[0];

    __half *qh, *kh, *vh, *xh, *wh;
    float *tS, *tC;
    cudaGetSymbolAddress((void**)&qh, g_Qh);
    cudaGetSymbolAddress((void**)&kh, g_Kh);
    cudaGetSymbolAddress((void**)&vh, g_Vh);
    cudaGetSymbolAddress((void**)&xh, g_xh);
    cudaGetSymbolAddress((void**)&wh, g_wh);
    cudaGetSymbolAddress((void**)&tS, g_tS);
    cudaGetSymbolAddress((void**)&tC, g_tC);

    const int nx4 = MTOT*HID/4;
    const int nw4 = HID*HID/4;
    const size_t wstride = (size_t)HID*HID;

    cvt_kernel<<<nx4/256, 256>>>(x, xh, nx4);
    cvt_w_kernel<<<dim3(nw4/256, 4), 256>>>((const float*)d_in[1], (const float*)d_in[2],
                                            (const float*)d_in[3], (const float*)d_in[4],
                                            wh, nw4);
    rope_tbl_kernel<<<SEQ*64/256, 256>>>(tS, tC);

    cudaFuncSetAttribute(gemm_fp16_kernel, cudaFuncAttributeMaxDynamicSharedMemorySize,
                         G_SMEM);

    // Fused QKV projection + rope epilogue: writes qh/kh/vh fp16 directly
    gemm_fp16_kernel<<<dim3(3*HID/128, MTOT/128), 256, G_SMEM>>>(
        xh, wh, qh, kh, vh, nullptr, tS, tC, 0);

    cudaFuncSetAttribute(attn_f16_kernel, cudaFuncAttributeMaxDynamicSharedMemorySize,
                         ATTN_SMEM);
    // attn writes fp16 output into xh (x no longer needed)
    attn_f16_kernel<<<dim3(SEQ/ABR, BATCH*NHEAD), 256, ATTN_SMEM>>>(qh, kh, vh, xh);

    // O projection (fp32 row-major to d_out)
    gemm_fp16_kernel<<<dim3(HID/128, MTOT/128), 256, G_SMEM>>>(
        xh, wh + 3*wstride, nullptr, nullptr, nullptr, (float*)d_out,
        nullptr, nullptr, 1);
}

// round 15
// speedup vs baseline: 1.1359x; 1.0033x over previous
#include <cuda_runtime.h>
#include <cuda_fp16.h>
#include <math.h>

// Problem constants
#define BATCH 4
#define SEQ   2048
#define HID   2048
#define NHEAD 16
#define HD    128
#define MTOT  (BATCH*SEQ)        // 8192
#define SCALE 0.08838834764831845f   // 1/sqrt(128)

// Scratch buffers
__device__ __half g_Qh[(size_t)BATCH*NHEAD*SEQ*HD];  // fp16 [bh][s][d] (post-rope)
__device__ __half g_Kh[(size_t)BATCH*NHEAD*SEQ*HD];
__device__ __half g_Vh[(size_t)BATCH*NHEAD*SEQ*HD];  // fp16 [bh][s][d]
__device__ __half g_xh[(size_t)MTOT*HID];            // x fp16; reused as AO fp16
__device__ __half g_wh[4][(size_t)HID*HID];          // weights fp16 (contiguous slabs)
__device__ float  g_tS[(size_t)SEQ*64];              // rope sin table [s][j]
__device__ float  g_tC[(size_t)SEQ*64];              // rope cos table [s][j]

// ---------------------------------------------------------------------------
// PTX helpers
// ---------------------------------------------------------------------------
__device__ __forceinline__ unsigned smem_u32(const void* p) {
    unsigned a;
    asm("{ .reg .u64 t; cvta.to.shared.u64 t, %1; cvt.u32.u64 %0, t; }"
        : "=r"(a) : "l"(p));
    return a;
}

__device__ __forceinline__ void cp16(unsigned dst, const void* src) {
    asm volatile("cp.async.cg.shared.global [%0], [%1], 16;\n"
                 :: "r"(dst), "l"(src) : "memory");
}
#define CP_COMMIT() asm volatile("cp.async.commit_group;\n" ::: "memory")
#define CP_WAIT2()  asm volatile("cp.async.wait_group 2;\n" ::: "memory")
#define CP_WAIT1()  asm volatile("cp.async.wait_group 1;\n" ::: "memory")
#define CP_WAIT0()  asm volatile("cp.async.wait_group 0;\n" ::: "memory")

__device__ __forceinline__ void ldm_x4(unsigned& r0, unsigned& r1,
                                       unsigned& r2, unsigned& r3, unsigned addr) {
    asm volatile("ldmatrix.sync.aligned.m8n8.x4.shared.b16 {%0,%1,%2,%3}, [%4];"
                 : "=r"(r0), "=r"(r1), "=r"(r2), "=r"(r3) : "r"(addr));
}
__device__ __forceinline__ void ldm_x4_t(unsigned& r0, unsigned& r1,
                                         unsigned& r2, unsigned& r3, unsigned addr) {
    asm volatile("ldmatrix.sync.aligned.m8n8.x4.trans.shared.b16 {%0,%1,%2,%3}, [%4];"
                 : "=r"(r0), "=r"(r1), "=r"(r2), "=r"(r3) : "r"(addr));
}

__device__ __forceinline__ void mma_f16(float (&d)[4], const unsigned (&a)[4],
                                        const unsigned (&b)[2]) {
    asm volatile(
        "mma.sync.aligned.m16n8k16.row.col.f32.f16.f16.f32 "
        "{%0,%1,%2,%3}, {%4,%5,%6,%7}, {%8,%9}, {%0,%1,%2,%3};\n"
        : "+f"(d[0]), "+f"(d[1]), "+f"(d[2]), "+f"(d[3])
        : "r"(a[0]), "r"(a[1]), "r"(a[2]), "r"(a[3]),
          "r"(b[0]), "r"(b[1]));
}

// ---------------------------------------------------------------------------
// Conversions + rope table
// ---------------------------------------------------------------------------
__global__ void cvt_kernel(const float* __restrict__ src,
                           __half* __restrict__ dst, int n4)
{
    const int i = blockIdx.x * blockDim.x + threadIdx.x;
    if (i >= n4) return;
    float4 v = ((const float4*)src)[i];
    __half2* d = (__half2*)&dst[(size_t)4*i];
    d[0] = __floats2half2_rn(v.x, v.y);
    d[1] = __floats2half2_rn(v.z, v.w);
}

__global__ void cvt_w_kernel(const float* __restrict__ w0, const float* __restrict__ w1,
                             const float* __restrict__ w2, const float* __restrict__ w3,
                             __half* __restrict__ dst, int n4)
{
    const int i = blockIdx.x * blockDim.x + threadIdx.x;
    if (i >= n4) return;
    const float* src = (blockIdx.y == 0) ? w0 : (blockIdx.y == 1) ? w1
                     : (blockIdx.y == 2) ? w2 : w3;
    float4 v = ((const float4*)src)[i];
    __half2* d = (__half2*)&dst[(size_t)blockIdx.y * (HID*(size_t)HID) + (size_t)4*i];
    d[0] = __floats2half2_rn(v.x, v.y);
    d[1] = __floats2half2_rn(v.z, v.w);
}

// sin/cos tables, exact same value chain as the original rope kernel
__global__ void rope_tbl_kernel(float* __restrict__ tS, float* __restrict__ tC)
{
    const int idx = blockIdx.x * blockDim.x + threadIdx.x;   // s*64 + j
    const int s = idx >> 6, j = idx & 63;
    const double e = -((double)(2*j) / 128.0) * 9.210340371976184;  // ln(10000)
    const float inv = (float)exp(e);
    const float ang = (float)s * inv;
    float sn, cs;
    sincosf(ang, &sn, &cs);
    tS[idx] = sn;
    tC[idx] = cs;
}

// ---------------------------------------------------------------------------
// fp16 tensor GEMM (NT) — ROUND-10 CONFIG, FROZEN.
// CTA tile 128x128, warp tile 64x32, GBK=32, 4-stage ring, 2 CTAs/SM.
// mode 0 (fused QKV): N=6144; proj = n0>>11:
//   0/1 -> staged rope epilogue, fp16 to qh/kh ([bh][s][d]);  2 -> fp16 to vh
// mode 1: fp32 row-major [M, HID] to fOut.
// ---------------------------------------------------------------------------
#define GBK 32
#define GROWB 80                         // bytes per smem row (40 halves)
#define GTILE_B (128*GROWB)              // 10240
#define GSTAGE_B (2*GTILE_B)             // 20480
#define G_SMEM (4*GSTAGE_B)              // 81920 (>= 128*130*4 = 66560 staging)
#define GNK (HID/GBK)                    // 64
#define STG_STRIDE 130                   // floats per staged row

__global__ __launch_bounds__(256, 2)
void gemm_fp16_kernel(const __half* __restrict__ Ah, const __half* __restrict__ Wh,
                      __half* __restrict__ qOut, __half* __restrict__ kOut,
                      __half* __restrict__ vOut, float* __restrict__ fOut,
                      const float* __restrict__ tblS, const float* __restrict__ tblC,
                      int mode)
{
    extern __shared__ __align__(16) char smem[];
    const unsigned sbase = smem_u32(smem);
    const int tid = threadIdx.x;
    const int warp = tid >> 5, lane = tid & 31;
    const int m0 = blockIdx.y * 128;
    const int n0 = blockIdx.x * 128;
    const int wm = (warp >> 2) * 64;
    const int wn = (warp & 3) * 32;
    const int g = lane >> 2, c = lane & 3;

    float acc[4][4][4];
#pragma unroll
    for (int mt = 0; mt < 4; mt++)
#pragma unroll
        for (int nt = 0; nt < 4; nt++)
#pragma unroll
            for (int e = 0; e < 4; e++) acc[mt][nt][e] = 0.f;

    const int lrow = tid >> 1;
    const int lofs = (tid & 1) << 4;
    const __half* Ar = Ah + (size_t)(m0 + lrow) * HID + lofs;
    const __half* Wr = Wh + (size_t)(n0 + lrow) * HID + lofs;
    const unsigned sm_off = (unsigned)lrow * GROWB + (unsigned)(tid & 1) * 32;

    auto load_stage = [&](int q) {
        const unsigned s = sbase + (q & 3) * GSTAGE_B;
        const __half* a = Ar + q * GBK;
        const __half* w = Wr + q * GBK;
        cp16(s + sm_off,                a);
        cp16(s + sm_off + 16,           a + 8);
        cp16(s + GTILE_B + sm_off,      w);
        cp16(s + GTILE_B + sm_off + 16, w + 8);
    };

    load_stage(0); CP_COMMIT();
    load_stage(1); CP_COMMIT();
    load_stage(2); CP_COMMIT();

    const unsigned aRowOff = (unsigned)(wm + (lane & 15)) * GROWB
                           + ((unsigned)(lane >> 4) << 4);
    const unsigned bRowOff = (unsigned)(wn + (lane & 7) + ((lane >> 4) << 3)) * GROWB
                           + (unsigned)((lane >> 3) & 1) * 16;

    for (int q = 0; q < GNK; q++) {
        CP_WAIT2();
        __syncthreads();
        if (q + 3 < GNK) load_stage(q + 3);
        CP_COMMIT();

        const unsigned sa = sbase + (q & 3) * GSTAGE_B;
        const unsigned sb = sa + GTILE_B;

        unsigned a0[4][4], a1[4][4], b0[4][2], b1[4][2];
#pragma unroll
        for (int mt = 0; mt < 4; mt++) {
            const unsigned base = sa + aRowOff + (unsigned)(16*mt) * GROWB;
            ldm_x4(a0[mt][0], a0[mt][1], a0[mt][2], a0[mt][3], base);
            ldm_x4(a1[mt][0], a1[mt][1], a1[mt][2], a1[mt][3], base + 32);
        }
#pragma unroll
        for (int nt2 = 0; nt2 < 2; nt2++) {
            const unsigned base = sb + bRowOff + (unsigned)(16*nt2) * GROWB;
            ldm_x4(b0[2*nt2][0], b0[2*nt2][1], b0[2*nt2+1][0], b0[2*nt2+1][1], base);
            ldm_x4(b1[2*nt2][0], b1[2*nt2][1], b1[2*nt2+1][0], b1[2*nt2+1][1], base + 32);
        }

#pragma unroll
        for (int mt = 0; mt < 4; mt++)
#pragma unroll
            for (int nt = 0; nt < 4; nt++)
                mma_f16(acc[mt][nt], a0[mt], b0[nt]);
#pragma unroll
        for (int mt = 0; mt < 4; mt++)
#pragma unroll
            for (int nt = 0; nt < 4; nt++)
                mma_f16(acc[mt][nt], a1[mt], b1[nt]);
    }

    // ---------------- Epilogue ----------------
    if (mode == 1) {
#pragma unroll
        for (int mt = 0; mt < 4; mt++)
#pragma unroll
            for (int nt = 0; nt < 4; nt++) {
                const int row = m0 + wm + mt*16 + g;
                const int col = n0 + wn + nt*8 + 2*c;
                *(float2*)(fOut + (size_t)row * HID + col) =
                    make_float2(acc[mt][nt][0], acc[mt][nt][1]);
                *(float2*)(fOut + (size_t)(row + 8) * HID + col) =
                    make_float2(acc[mt][nt][2], acc[mt][nt][3]);
            }
        return;
    }

    const int proj = n0 >> 11;           // 0=Q 1=K 2=V (uniform per CTA)
    const int h = (n0 & 2047) >> 7;

    if (proj == 2) {
#pragma unroll
        for (int mt = 0; mt < 4; mt++)
#pragma unroll
            for (int nt = 0; nt < 4; nt++) {
                const int row = m0 + wm + mt*16 + g;
                const int col = n0 + wn + nt*8 + 2*c;
                const int cw = col & 2047;
                const int b = row >> 11;
                const int s = row & (SEQ-1);
                const int d = cw & (HD-1);
                __half* dst = vOut + (((size_t)(b*NHEAD + h))*SEQ + s)*HD + d;
                *(__half2*)dst = __floats2half2_rn(acc[mt][nt][0], acc[mt][nt][1]);
                *(__half2*)(dst + (size_t)8*HD) =
                    __floats2half2_rn(acc[mt][nt][2], acc[mt][nt][3]);
            }
        return;
    }

    // Q/K: stage fp32 tile in smem, apply rope from tables, write fp16
    __syncthreads();
    float* st = (float*)smem;            // 128 x STG_STRIDE
#pragma unroll
    for (int mt = 0; mt < 4; mt++)
#pragma unroll
        for (int nt = 0; nt < 4; nt++) {
            const int r = wm + mt*16 + g;
            const int col = wn + nt*8 + 2*c;
            *(float2*)&st[r*STG_STRIDE + col] =
                make_float2(acc[mt][nt][0], acc[mt][nt][1]);
            *(float2*)&st[(r + 8)*STG_STRIDE + col] =
                make_float2(acc[mt][nt][2], acc[mt][nt][3]);
        }
    __syncthreads();

    __half* outh = proj ? kOut : qOut;
    const int j = 2 * lane;
#pragma unroll 4
    for (int it = 0; it < 16; it++) {
        const int r = warp * 16 + it;
        const int row = m0 + r;
        const int b = row >> 11;
        const int s = row & (SEQ-1);
        float2 sn2 = *(const float2*)&tblS[s*64 + j];
        float2 cs2 = *(const float2*)&tblC[s*64 + j];
        float q1a = st[r*STG_STRIDE + j],      q1b = st[r*STG_STRIDE + j + 1];
        float q2a = st[r*STG_STRIDE + j + 64], q2b = st[r*STG_STRIDE + j + 65];
        __half2 lo = __floats2half2_rn(q1a*sn2.x - q2a*cs2.x, q1b*sn2.y - q2b*cs2.y);
        __half2 hi = __floats2half2_rn(q1a*cs2.x + q2a*sn2.x, q1b*cs2.y + q2b*sn2.y);
        __half* dst = outh + (((size_t)(b*NHEAD + h))*SEQ + s)*HD;
        *(__half2*)&dst[j]      = lo;
        *(__half2*)&dst[j + 64] = hi;
    }
}

// ---------------------------------------------------------------------------
// Causal flash attention, fp16 mma + 2-stage cp.async KV ring.
// WORK PAIRING: each CTA runs TWO q-tiles — (NBX-1-bx) then (bx) — so every
// CTA does exactly 34 tile-iterations (uniform grid, no ragged tail).
// Grid (8, 64) = 512 CTAs. Per-tile arithmetic identical to round 12.
// ---------------------------------------------------------------------------
#define ABR 128
#define ABC 64
#define AQSTR 136                       // halves; 272B row stride (16B-aligned)
#define APSTR 72
#define SQ_BYTES (ABR*AQSTR*2)          // 34816
#define SK_BYTES (ABC*AQSTR*2)          // 17408
#define KV_STAGE (2*SK_BYTES)           // 34816
#define ATTN_SMEM (SQ_BYTES + 2*KV_STAGE)   // 104448
#define NBX (SEQ/ABR)                   // 16

__global__ __launch_bounds__(256, 1)
void attn_f16_kernel(const __half* __restrict__ Qh, const __half* __restrict__ Kh,
                     const __half* __restrict__ Vh, __half* __restrict__ out)
{
    extern __shared__ __align__(16) char smem[];
    __half* sP = (__half*)smem;                  // aliases dead sQ
    const unsigned uQ = smem_u32(smem);
    const unsigned uKV = uQ + SQ_BYTES;
    const unsigned uP = uQ;

    const int bh = blockIdx.y;
    const int tid = threadIdx.x;
    const int warp = tid >> 5, lane = tid & 31;
    const int g = lane >> 2, c = lane & 3;
    const int wm = warp * 16;

    const __half* Qb = Qh + (size_t)bh * SEQ * HD;
    const __half* Kb = Kh + (size_t)bh * SEQ * HD;
    const __half* Vb = Vh + (size_t)bh * SEQ * HD;

    const int b = bh >> 4;
    const int h = bh & 15;

    auto load_kv = [&](int kt, int stage) {
        const int k0 = kt * ABC;
        const unsigned s = uKV + stage * KV_STAGE;
#pragma unroll
        for (int i = 0; i < 4; i++) {
            const int idx = tid + 256*i;         // 0..1023
            const int r = idx >> 4, ch = idx & 15;
            const unsigned so = (unsigned)r * (AQSTR*2) + (unsigned)ch * 16;
            cp16(s + so,            Kb + (size_t)(k0 + r)*HD + ch*8);
            cp16(s + SK_BYTES + so, Vb + (size_t)(k0 + r)*HD + ch*8);
        }
    };

#pragma unroll 1
    for (int pass = 0; pass < 2; pass++) {
        // long tile first, then its short partner
        const int bx = (pass == 0) ? (NBX - 1 - (int)blockIdx.x) : (int)blockIdx.x;
        const int q0 = bx * ABR;

        __syncthreads();   // pass-0's sP/KV reads done before reusing smem

        // Prologue: async Q tile, then KV tile 0
#pragma unroll
        for (int i = 0; i < 8; i++) {
            const int idx = tid + 256*i;         // 0..2047
            const int r = idx >> 4, ch = idx & 15;
            cp16(uQ + (unsigned)r*(AQSTR*2) + (unsigned)ch*16,
                 Qb + (size_t)(q0 + r)*HD + ch*8);
        }
        CP_COMMIT();
        load_kv(0, 0);
        CP_COMMIT();
        CP_WAIT1();                 // Q group complete
        __syncthreads();

        // Hoist Q fragments; sQ is dead afterwards
        unsigned qa[8][4];
#pragma unroll
        for (int k16 = 0; k16 < 8; k16++) {
            const unsigned addr = uQ + (unsigned)(wm + (lane & 15)) * (AQSTR*2)
                                + (unsigned)k16 * 32 + ((unsigned)(lane >> 4) << 4);
            ldm_x4(qa[k16][0], qa[k16][1], qa[k16][2], qa[k16][3], addr);
        }

        float m_r[2] = { -1e30f, -1e30f };
        float l_r[2] = { 0.f, 0.f };
        float acco[16][4];
#pragma unroll
        for (int nt = 0; nt < 16; nt++)
#pragma unroll
            for (int e = 0; e < 4; e++) acco[nt][e] = 0.f;

        const int qi0 = q0 + wm + g;
        const int qi1 = qi0 + 8;
        const int ktmax = q0/ABC + 1;

        for (int kt = 0; kt <= ktmax; kt++) {
            const int k0 = kt * ABC;
            CP_WAIT0();             // tile kt resident
            __syncthreads();        // all threads done reading stage (kt+1)&1
            if (kt + 1 <= ktmax) load_kv(kt + 1, (kt + 1) & 1);
            CP_COMMIT();

            const unsigned uK = uKV + (kt & 1) * KV_STAGE;
            const unsigned uV = uK + SK_BYTES;

            if (k0 > q0 + wm + 15) continue;   // warp tile fully masked

            // ---- S = Q K^T ----
            float accs[8][4];
#pragma unroll
            for (int nt = 0; nt < 8; nt++)
#pragma unroll
                for (int e = 0; e < 4; e++) accs[nt][e] = 0.f;

#pragma unroll
            for (int k16 = 0; k16 < 8; k16++) {
                unsigned bf[8][2];
#pragma unroll
                for (int nt2 = 0; nt2 < 4; nt2++) {
                    const unsigned addr = uK
                        + (unsigned)(16*nt2 + (lane & 7) + ((lane >> 4) << 3)) * (AQSTR*2)
                        + (unsigned)k16 * 32 + (unsigned)((lane >> 3) & 1) * 16;
                    ldm_x4(bf[2*nt2][0], bf[2*nt2][1], bf[2*nt2+1][0], bf[2*nt2+1][1], addr);
                }
#pragma unroll
                for (int nt = 0; nt < 8; nt++)
                    mma_f16(accs[nt], qa[k16], bf[nt]);
            }

            // ---- scale + causal mask + row max ----
            float mx0 = m_r[0], mx1 = m_r[1];
#pragma unroll
            for (int nt = 0; nt < 8; nt++) {
                const int colb = k0 + 8*nt + 2*c;
                float v0 = accs[nt][0] * SCALE; if (colb     > qi0) v0 = -1e30f;
                float v1 = accs[nt][1] * SCALE; if (colb + 1 > qi0) v1 = -1e30f;
                float v2 = accs[nt][2] * SCALE; if (colb     > qi1) v2 = -1e30f;
                float v3 = accs[nt][3] * SCALE; if (colb + 1 > qi1) v3 = -1e30f;
                accs[nt][0] = v0; accs[nt][1] = v1; accs[nt][2] = v2; accs[nt][3] = v3;
                mx0 = fmaxf(mx0, fmaxf(v0, v1));
                mx1 = fmaxf(mx1, fmaxf(v2, v3));
            }
            mx0 = fmaxf(mx0, __shfl_xor_sync(0xffffffffu, mx0, 1));
            mx0 = fmaxf(mx0, __shfl_xor_sync(0xffffffffu, mx0, 2));
            mx1 = fmaxf(mx1, __shfl_xor_sync(0xffffffffu, mx1, 1));
            mx1 = fmaxf(mx1, __shfl_xor_sync(0xffffffffu, mx1, 2));

            const float alpha0 = __expf(m_r[0] - mx0);
            const float alpha1 = __expf(m_r[1] - mx1);
            m_r[0] = mx0; m_r[1] = mx1;

            // ---- exp; round P to fp16; l sums the ROUNDED p ----
            float ls0 = 0.f, ls1 = 0.f;
#pragma unroll
            for (int nt = 0; nt < 8; nt++) {
                __half2 p01 = __floats2half2_rn(__expf(accs[nt][0] - mx0),
                                                __expf(accs[nt][1] - mx0));
                __half2 p23 = __floats2half2_rn(__expf(accs[nt][2] - mx1),
                                                __expf(accs[nt][3] - mx1));
                float2 f01 = __half22float2(p01);
                float2 f23 = __half22float2(p23);
                ls0 += f01.x + f01.y;
                ls1 += f23.x + f23.y;
                *(__half2*)&sP[(wm + g    )*APSTR + 8*nt + 2*c] = p01;
                *(__half2*)&sP[(wm + g + 8)*APSTR + 8*nt + 2*c] = p23;
            }
            ls0 += __shfl_xor_sync(0xffffffffu, ls0, 1);
            ls0 += __shfl_xor_sync(0xffffffffu, ls0, 2);
            ls1 += __shfl_xor_sync(0xffffffffu, ls1, 1);
            ls1 += __shfl_xor_sync(0xffffffffu, ls1, 2);
            l_r[0] = l_r[0] * alpha0 + ls0;
            l_r[1] = l_r[1] * alpha1 + ls1;

#pragma unroll
            for (int nt = 0; nt < 16; nt++) {
                acco[nt][0] *= alpha0; acco[nt][1] *= alpha0;
                acco[nt][2] *= alpha1; acco[nt][3] *= alpha1;
            }
            __syncwarp();   // sP rows are warp-private

            // ---- O += P V ----
#pragma unroll
            for (int k16 = 0; k16 < 4; k16++) {
                unsigned a[4];
                {
                    const unsigned addr = uP + (unsigned)(wm + (lane & 15)) * (APSTR*2)
                                        + (unsigned)k16 * 32 + ((unsigned)(lane >> 4) << 4);
                    ldm_x4(a[0], a[1], a[2], a[3], addr);
                }
#pragma unroll
                for (int nt2 = 0; nt2 < 8; nt2++) {
                    unsigned bf[2][2];
                    const unsigned addr = uV
                        + (unsigned)(k16*16 + (lane & 7) + (((lane >> 3) & 1) << 3)) * (AQSTR*2)
                        + (unsigned)(2*nt2 + (lane >> 4)) * 16;
                    ldm_x4_t(bf[0][0], bf[0][1], bf[1][0], bf[1][1], addr);
                    mma_f16(acco[2*nt2],     a, bf[0]);
                    mma_f16(acco[2*nt2 + 1], a, bf[1]);
                }
            }
        }

        // Epilogue: normalize, write fp16 [B*S, H]
        const float inv0 = 1.f / l_r[0];
        const float inv1 = 1.f / l_r[1];
        __half* base0 = out + ((size_t)(b*SEQ + q0 + wm + g    ))*HID + h*HD;
        __half* base1 = out + ((size_t)(b*SEQ + q0 + wm + g + 8))*HID + h*HD;
#pragma unroll
        for (int nt = 0; nt < 16; nt++) {
            *(__half2*)&base0[8*nt + 2*c] =
                __floats2half2_rn(acco[nt][0]*inv0, acco[nt][1]*inv0);
            *(__half2*)&base1[8*nt + 2*c] =
                __floats2half2_rn(acco[nt][2]*inv1, acco[nt][3]*inv1);
        }
    }
}

// ---------------------------------------------------------------------------
// Launch
// ---------------------------------------------------------------------------
extern "C" void kernel_launch(void* const* d_in, const int* in_sizes, int n_in,
                              void* d_out, int out_size)
{
    const float* x  = (const float*)d_in[0];

    __half *qh, *kh, *vh, *xh, *wh;
    float *tS, *tC;
    cudaGetSymbolAddress((void**)&qh, g_Qh);
    cudaGetSymbolAddress((void**)&kh, g_Kh);
    cudaGetSymbolAddress((void**)&vh, g_Vh);
    cudaGetSymbolAddress((void**)&xh, g_xh);
    cudaGetSymbolAddress((void**)&wh, g_wh);
    cudaGetSymbolAddress((void**)&tS, g_tS);
    cudaGetSymbolAddress((void**)&tC, g_tC);

    const int nx4 = MTOT*HID/4;
    const int nw4 = HID*HID/4;
    const size_t wstride = (size_t)HID*HID;

    cvt_kernel<<<nx4/256, 256>>>(x, xh, nx4);
    cvt_w_kernel<<<dim3(nw4/256, 4), 256>>>((const float*)d_in[1], (const float*)d_in[2],
                                            (const float*)d_in[3], (const float*)d_in[4],
                                            wh, nw4);
    rope_tbl_kernel<<<SEQ*64/256, 256>>>(tS, tC);

    cudaFuncSetAttribute(gemm_fp16_kernel, cudaFuncAttributeMaxDynamicSharedMemorySize,
                         G_SMEM);

    // Fused QKV projection + rope epilogue: writes qh/kh/vh fp16 directly
    gemm_fp16_kernel<<<dim3(3*HID/128, MTOT/128), 256, G_SMEM>>>(
        xh, wh, qh, kh, vh, nullptr, tS, tC, 0);

    cudaFuncSetAttribute(attn_f16_kernel, cudaFuncAttributeMaxDynamicSharedMemorySize,
                         ATTN_SMEM);
    // attn writes fp16 output into xh (x no longer needed); paired q-tiles
    attn_f16_kernel<<<dim3(NBX/2, BATCH*NHEAD), 256, ATTN_SMEM>>>(qh, kh, vh, xh);

    // O projection (fp32 row-major to d_out)
    gemm_fp16_kernel<<<dim3(HID/128, MTOT/128), 256, G_SMEM>>>(
        xh, wh + 3*wstride, nullptr, nullptr, nullptr, (float*)d_out,
        nullptr, nullptr, 1);
}

// round 16
// speedup vs baseline: 1.1482x; 1.0108x over previous
#include <cuda_runtime.h>
#include <cuda_fp16.h>
#include <math.h>

// Problem constants
#define BATCH 4
#define SEQ   2048
#define HID   2048
#define NHEAD 16
#define HD    128
#define MTOT  (BATCH*SEQ)        // 8192
#define SCALE 0.08838834764831845f   // 1/sqrt(128)

// Scratch buffers
__device__ __half g_Qh[(size_t)BATCH*NHEAD*SEQ*HD];  // fp16 [bh][s][d] (post-rope)
__device__ __half g_Kh[(size_t)BATCH*NHEAD*SEQ*HD];
__device__ __half g_Vh[(size_t)BATCH*NHEAD*SEQ*HD];  // fp16 [bh][s][d]
__device__ __half g_xh[(size_t)MTOT*HID];            // x fp16; reused as AO fp16
__device__ __half g_wh[4][(size_t)HID*HID];          // weights fp16 (contiguous slabs)
__device__ float  g_tS[(size_t)SEQ*64];              // rope sin table [s][j]
__device__ float  g_tC[(size_t)SEQ*64];              // rope cos table [s][j]

// ---------------------------------------------------------------------------
// PTX helpers
// ---------------------------------------------------------------------------
__device__ __forceinline__ unsigned smem_u32(const void* p) {
    unsigned a;
    asm("{ .reg .u64 t; cvta.to.shared.u64 t, %1; cvt.u32.u64 %0, t; }"
        : "=r"(a) : "l"(p));
    return a;
}

__device__ __forceinline__ void cp16(unsigned dst, const void* src) {
    asm volatile("cp.async.cg.shared.global [%0], [%1], 16;\n"
                 :: "r"(dst), "l"(src) : "memory");
}
#define CP_COMMIT() asm volatile("cp.async.commit_group;\n" ::: "memory")
#define CP_WAIT2()  asm volatile("cp.async.wait_group 2;\n" ::: "memory")
#define CP_WAIT1()  asm volatile("cp.async.wait_group 1;\n" ::: "memory")
#define CP_WAIT0()  asm volatile("cp.async.wait_group 0;\n" ::: "memory")

__device__ __forceinline__ void ldm_x4(unsigned& r0, unsigned& r1,
                                       unsigned& r2, unsigned& r3, unsigned addr) {
    asm volatile("ldmatrix.sync.aligned.m8n8.x4.shared.b16 {%0,%1,%2,%3}, [%4];"
                 : "=r"(r0), "=r"(r1), "=r"(r2), "=r"(r3) : "r"(addr));
}
__device__ __forceinline__ void ldm_x4_t(unsigned& r0, unsigned& r1,
                                         unsigned& r2, unsigned& r3, unsigned addr) {
    asm volatile("ldmatrix.sync.aligned.m8n8.x4.trans.shared.b16 {%0,%1,%2,%3}, [%4];"
                 : "=r"(r0), "=r"(r1), "=r"(r2), "=r"(r3) : "r"(addr));
}

__device__ __forceinline__ void mma_f16(float (&d)[4], const unsigned (&a)[4],
                                        const unsigned (&b)[2]) {
    asm volatile(
        "mma.sync.aligned.m16n8k16.row.col.f32.f16.f16.f32 "
        "{%0,%1,%2,%3}, {%4,%5,%6,%7}, {%8,%9}, {%0,%1,%2,%3};\n"
        : "+f"(d[0]), "+f"(d[1]), "+f"(d[2]), "+f"(d[3])
        : "r"(a[0]), "r"(a[1]), "r"(a[2]), "r"(a[3]),
          "r"(b[0]), "r"(b[1]));
}

// ---------------------------------------------------------------------------
// Fused prep: x->fp16, 4 weights->fp16, rope tables. One launch.
// 4 float4 per thread (MLP=4) for the streaming parts; identical rounding
// chains to the previous separate kernels (bit-exact outputs).
// Grid: [0,4096) x-cvt | [4096,8192) w-cvt | [8192,8704) rope tables.
// ---------------------------------------------------------------------------
#define PREP_X_CTAS 4096                 // 1,048,576 threads; 4 float4 each
#define PREP_W_CTAS_PER 1024             // per weight; 262,144 threads; 4 each
#define PREP_GRID (PREP_X_CTAS + 4*PREP_W_CTAS_PER + 512)

__global__ void prep_kernel(const float* __restrict__ x,
                            const float* __restrict__ w0, const float* __restrict__ w1,
                            const float* __restrict__ w2, const float* __restrict__ w3,
                            __half* __restrict__ xh, __half* __restrict__ wh,
                            float* __restrict__ tS, float* __restrict__ tC)
{
    const int bx = blockIdx.x;
    if (bx < PREP_X_CTAS) {
        // x: nx4 = 4,194,304 float4 elements
        const int t = bx * 256 + threadIdx.x;          // 0..1,048,575
        const int N = PREP_X_CTAS * 256;
        float4 v[4];
#pragma unroll
        for (int j = 0; j < 4; j++) v[j] = ((const float4*)x)[t + j*N];
#pragma unroll
        for (int j = 0; j < 4; j++) {
            __half2* d = (__half2*)&xh[(size_t)4 * (t + j*N)];
            d[0] = __floats2half2_rn(v[j].x, v[j].y);
            d[1] = __floats2half2_rn(v[j].z, v[j].w);
        }
    } else if (bx < PREP_X_CTAS + 4*PREP_W_CTAS_PER) {
        // weights: nw4 = 1,048,576 float4 elements each
        const int wb = bx - PREP_X_CTAS;
        const int wi = wb >> 10;                       // 0..3
        const int lb = wb & 1023;
        const float* src = (wi == 0) ? w0 : (wi == 1) ? w1 : (wi == 2) ? w2 : w3;
        __half* dstW = wh + (size_t)wi * (HID*(size_t)HID);
        const int t = lb * 256 + threadIdx.x;          // 0..262,143
        const int N = PREP_W_CTAS_PER * 256;
        float4 v[4];
#pragma unroll
        for (int j = 0; j < 4; j++) v[j] = ((const float4*)src)[t + j*N];
#pragma unroll
        for (int j = 0; j < 4; j++) {
            __half2* d = (__half2*)&dstW[(size_t)4 * (t + j*N)];
            d[0] = __floats2half2_rn(v[j].x, v[j].y);
            d[1] = __floats2half2_rn(v[j].z, v[j].w);
        }
    } else {
        // rope tables: SEQ*64 = 131,072 entries; same value chain as before
        const int idx = (bx - PREP_X_CTAS - 4*PREP_W_CTAS_PER) * 256 + threadIdx.x;
        const int s = idx >> 6, j = idx & 63;
        const double e = -((double)(2*j) / 128.0) * 9.210340371976184;  // ln(10000)
        const float inv = (float)exp(e);
        const float ang = (float)s * inv;
        float sn, cs;
        sincosf(ang, &sn, &cs);
        tS[idx] = sn;
        tC[idx] = cs;
    }
}

// ---------------------------------------------------------------------------
// fp16 tensor GEMM (NT) — ROUND-10 CONFIG, FROZEN.
// CTA tile 128x128, warp tile 64x32, GBK=32, 4-stage ring, 2 CTAs/SM.
// mode 0 (fused QKV): N=6144; proj = n0>>11:
//   0/1 -> staged rope epilogue, fp16 to qh/kh ([bh][s][d]);  2 -> fp16 to vh
// mode 1: fp32 row-major [M, HID] to fOut.
// ---------------------------------------------------------------------------
#define GBK 32
#define GROWB 80                         // bytes per smem row (40 halves)
#define GTILE_B (128*GROWB)              // 10240
#define GSTAGE_B (2*GTILE_B)             // 20480
#define G_SMEM (4*GSTAGE_B)              // 81920 (>= 128*130*4 = 66560 staging)
#define GNK (HID/GBK)                    // 64
#define STG_STRIDE 130                   // floats per staged row

__global__ __launch_bounds__(256, 2)
void gemm_fp16_kernel(const __half* __restrict__ Ah, const __half* __restrict__ Wh,
                      __half* __restrict__ qOut, __half* __restrict__ kOut,
                      __half* __restrict__ vOut, float* __restrict__ fOut,
                      const float* __restrict__ tblS, const float* __restrict__ tblC,
                      int mode)
{
    extern __shared__ __align__(16) char smem[];
    const unsigned sbase = smem_u32(smem);
    const int tid = threadIdx.x;
    const int warp = tid >> 5, lane = tid & 31;
    const int m0 = blockIdx.y * 128;
    const int n0 = blockIdx.x * 128;
    const int wm = (warp >> 2) * 64;
    const int wn = (warp & 3) * 32;
    const int g = lane >> 2, c = lane & 3;

    float acc[4][4][4];
#pragma unroll
    for (int mt = 0; mt < 4; mt++)
#pragma unroll
        for (int nt = 0; nt < 4; nt++)
#pragma unroll
            for (int e = 0; e < 4; e++) acc[mt][nt][e] = 0.f;

    const int lrow = tid >> 1;
    const int lofs = (tid & 1) << 4;
    const __half* Ar = Ah + (size_t)(m0 + lrow) * HID + lofs;
    const __half* Wr = Wh + (size_t)(n0 + lrow) * HID + lofs;
    const unsigned sm_off = (unsigned)lrow * GROWB + (unsigned)(tid & 1) * 32;

    auto load_stage = [&](int q) {
        const unsigned s = sbase + (q & 3) * GSTAGE_B;
        const __half* a = Ar + q * GBK;
        const __half* w = Wr + q * GBK;
        cp16(s + sm_off,                a);
        cp16(s + sm_off + 16,           a + 8);
        cp16(s + GTILE_B + sm_off,      w);
        cp16(s + GTILE_B + sm_off + 16, w + 8);
    };

    load_stage(0); CP_COMMIT();
    load_stage(1); CP_COMMIT();
    load_stage(2); CP_COMMIT();

    const unsigned aRowOff = (unsigned)(wm + (lane & 15)) * GROWB
                           + ((unsigned)(lane >> 4) << 4);
    const unsigned bRowOff = (unsigned)(wn + (lane & 7) + ((lane >> 4) << 3)) * GROWB
                           + (unsigned)((lane >> 3) & 1) * 16;

    for (int q = 0; q < GNK; q++) {
        CP_WAIT2();
        __syncthreads();
        if (q + 3 < GNK) load_stage(q + 3);
        CP_COMMIT();

        const unsigned sa = sbase + (q & 3) * GSTAGE_B;
        const unsigned sb = sa + GTILE_B;

        unsigned a0[4][4], a1[4][4], b0[4][2], b1[4][2];
#pragma unroll
        for (int mt = 0; mt < 4; mt++) {
            const unsigned base = sa + aRowOff + (unsigned)(16*mt) * GROWB;
            ldm_x4(a0[mt][0], a0[mt][1], a0[mt][2], a0[mt][3], base);
            ldm_x4(a1[mt][0], a1[mt][1], a1[mt][2], a1[mt][3], base + 32);
        }
#pragma unroll
        for (int nt2 = 0; nt2 < 2; nt2++) {
            const unsigned base = sb + bRowOff + (unsigned)(16*nt2) * GROWB;
            ldm_x4(b0[2*nt2][0], b0[2*nt2][1], b0[2*nt2+1][0], b0[2*nt2+1][1], base);
            ldm_x4(b1[2*nt2][0], b1[2*nt2][1], b1[2*nt2+1][0], b1[2*nt2+1][1], base + 32);
        }

#pragma unroll
        for (int mt = 0; mt < 4; mt++)
#pragma unroll
            for (int nt = 0; nt < 4; nt++)
                mma_f16(acc[mt][nt], a0[mt], b0[nt]);
#pragma unroll
        for (int mt = 0; mt < 4; mt++)
#pragma unroll
            for (int nt = 0; nt < 4; nt++)
                mma_f16(acc[mt][nt], a1[mt], b1[nt]);
    }

    // ---------------- Epilogue ----------------
    if (mode == 1) {
#pragma unroll
        for (int mt = 0; mt < 4; mt++)
#pragma unroll
            for (int nt = 0; nt < 4; nt++) {
                const int row = m0 + wm + mt*16 + g;
                const int col = n0 + wn + nt*8 + 2*c;
                *(float2*)(fOut + (size_t)row * HID + col) =
                    make_float2(acc[mt][nt][0], acc[mt][nt][1]);
                *(float2*)(fOut + (size_t)(row + 8) * HID + col) =
                    make_float2(acc[mt][nt][2], acc[mt][nt][3]);
            }
        return;
    }

    const int proj = n0 >> 11;           // 0=Q 1=K 2=V (uniform per CTA)
    const int h = (n0 & 2047) >> 7;

    if (proj == 2) {
#pragma unroll
        for (int mt = 0; mt < 4; mt++)
#pragma unroll
            for (int nt = 0; nt < 4; nt++) {
                const int row = m0 + wm + mt*16 + g;
                const int col = n0 + wn + nt*8 + 2*c;
                const int cw = col & 2047;
                const int b = row >> 11;
                const int s = row & (SEQ-1);
                const int d = cw & (HD-1);
                __half* dst = vOut + (((size_t)(b*NHEAD + h))*SEQ + s)*HD + d;
                *(__half2*)dst = __floats2half2_rn(acc[mt][nt][0], acc[mt][nt][1]);
                *(__half2*)(dst + (size_t)8*HD) =
                    __floats2half2_rn(acc[mt][nt][2], acc[mt][nt][3]);
            }
        return;
    }

    // Q/K: stage fp32 tile in smem, apply rope from tables, write fp16
    __syncthreads();
    float* st = (float*)smem;            // 128 x STG_STRIDE
#pragma unroll
    for (int mt = 0; mt < 4; mt++)
#pragma unroll
        for (int nt = 0; nt < 4; nt++) {
            const int r = wm + mt*16 + g;
            const int col = wn + nt*8 + 2*c;
            *(float2*)&st[r*STG_STRIDE + col] =
                make_float2(acc[mt][nt][0], acc[mt][nt][1]);
            *(float2*)&st[(r + 8)*STG_STRIDE + col] =
                make_float2(acc[mt][nt][2], acc[mt][nt][3]);
        }
    __syncthreads();

    __half* outh = proj ? kOut : qOut;
    const int j = 2 * lane;
#pragma unroll 4
    for (int it = 0; it < 16; it++) {
        const int r = warp * 16 + it;
        const int row = m0 + r;
        const int b = row >> 11;
        const int s = row & (SEQ-1);
        float2 sn2 = *(const float2*)&tblS[s*64 + j];
        float2 cs2 = *(const float2*)&tblC[s*64 + j];
        float q1a = st[r*STG_STRIDE + j],      q1b = st[r*STG_STRIDE + j + 1];
        float q2a = st[r*STG_STRIDE + j + 64], q2b = st[r*STG_STRIDE + j + 65];
        __half2 lo = __floats2half2_rn(q1a*sn2.x - q2a*cs2.x, q1b*sn2.y - q2b*cs2.y);
        __half2 hi = __floats2half2_rn(q1a*cs2.x + q2a*sn2.x, q1b*cs2.y + q2b*sn2.y);
        __half* dst = outh + (((size_t)(b*NHEAD + h))*SEQ + s)*HD;
        *(__half2*)&dst[j]      = lo;
        *(__half2*)&dst[j + 64] = hi;
    }
}

// ---------------------------------------------------------------------------
// Causal flash attention, fp16 mma + 2-stage cp.async KV ring.
// WORK PAIRING: each CTA runs TWO q-tiles — (NBX-1-bx) then (bx); 34 uniform
// tile-iterations per CTA. Grid (8, 64). (Round-15 version, verbatim.)
// ---------------------------------------------------------------------------
#define ABR 128
#define ABC 64
#define AQSTR 136                       // halves; 272B row stride (16B-aligned)
#define APSTR 72
#define SQ_BYTES (ABR*AQSTR*2)          // 34816
#define SK_BYTES (ABC*AQSTR*2)          // 17408
#define KV_STAGE (2*SK_BYTES)           // 34816
#define ATTN_SMEM (SQ_BYTES + 2*KV_STAGE)   // 104448
#define NBX (SEQ/ABR)                   // 16

__global__ __launch_bounds__(256, 1)
void attn_f16_kernel(const __half* __restrict__ Qh, const __half* __restrict__ Kh,
                     const __half* __restrict__ Vh, __half* __restrict__ out)
{
    extern __shared__ __align__(16) char smem[];
    __half* sP = (__half*)smem;                  // aliases dead sQ
    const unsigned uQ = smem_u32(smem);
    const unsigned uKV = uQ + SQ_BYTES;
    const unsigned uP = uQ;

    const int bh = blockIdx.y;
    const int tid = threadIdx.x;
    const int warp = tid >> 5, lane = tid & 31;
    const int g = lane >> 2, c = lane & 3;
    const int wm = warp * 16;

    const __half* Qb = Qh + (size_t)bh * SEQ * HD;
    const __half* Kb = Kh + (size_t)bh * SEQ * HD;
    const __half* Vb = Vh + (size_t)bh * SEQ * HD;

    const int b = bh >> 4;
    const int h = bh & 15;

    auto load_kv = [&](int kt, int stage) {
        const int k0 = kt * ABC;
        const unsigned s = uKV + stage * KV_STAGE;
#pragma unroll
        for (int i = 0; i < 4; i++) {
            const int idx = tid + 256*i;         // 0..1023
            const int r = idx >> 4, ch = idx & 15;
            const unsigned so = (unsigned)r * (AQSTR*2) + (unsigned)ch * 16;
            cp16(s + so,            Kb + (size_t)(k0 + r)*HD + ch*8);
            cp16(s + SK_BYTES + so, Vb + (size_t)(k0 + r)*HD + ch*8);
        }
    };

#pragma unroll 1
    for (int pass = 0; pass < 2; pass++) {
        const int bx = (pass == 0) ? (NBX - 1 - (int)blockIdx.x) : (int)blockIdx.x;
        const int q0 = bx * ABR;

        __syncthreads();   // previous pass's sP/KV reads done before smem reuse

        // Prologue: async Q tile, then KV tile 0
#pragma unroll
        for (int i = 0; i < 8; i++) {
            const int idx = tid + 256*i;         // 0..2047
            const int r = idx >> 4, ch = idx & 15;
            cp16(uQ + (unsigned)r*(AQSTR*2) + (unsigned)ch*16,
                 Qb + (size_t)(q0 + r)*HD + ch*8);
        }
        CP_COMMIT();
        load_kv(0, 0);
        CP_COMMIT();
        CP_WAIT1();                 // Q group complete
        __syncthreads();

        // Hoist Q fragments; sQ is dead afterwards
        unsigned qa[8][4];
#pragma unroll
        for (int k16 = 0; k16 < 8; k16++) {
            const unsigned addr = uQ + (unsigned)(wm + (lane & 15)) * (AQSTR*2)
                                + (unsigned)k16 * 32 + ((unsigned)(lane >> 4) << 4);
            ldm_x4(qa[k16][0], qa[k16][1], qa[k16][2], qa[k16][3], addr);
        }

        float m_r[2] = { -1e30f, -1e30f };
        float l_r[2] = { 0.f, 0.f };
        float acco[16][4];
#pragma unroll
        for (int nt = 0; nt < 16; nt++)
#pragma unroll
            for (int e = 0; e < 4; e++) acco[nt][e] = 0.f;

        const int qi0 = q0 + wm + g;
        const int qi1 = qi0 + 8;
        const int ktmax = q0/ABC + 1;

        for (int kt = 0; kt <= ktmax; kt++) {
            const int k0 = kt * ABC;
            CP_WAIT0();             // tile kt resident
            __syncthreads();        // all threads done reading stage (kt+1)&1
            if (kt + 1 <= ktmax) load_kv(kt + 1, (kt + 1) & 1);
            CP_COMMIT();

            const unsigned uK = uKV + (kt & 1) * KV_STAGE;
            const unsigned uV = uK + SK_BYTES;

            if (k0 > q0 + wm + 15) continue;   // warp tile fully masked

            // ---- S = Q K^T ----
            float accs[8][4];
#pragma unroll
            for (int nt = 0; nt < 8; nt++)
#pragma unroll
                for (int e = 0; e < 4; e++) accs[nt][e] = 0.f;

#pragma unroll
            for (int k16 = 0; k16 < 8; k16++) {
                unsigned bf[8][2];
#pragma unroll
                for (int nt2 = 0; nt2 < 4; nt2++) {
                    const unsigned addr = uK
                        + (unsigned)(16*nt2 + (lane & 7) + ((lane >> 4) << 3)) * (AQSTR*2)
                        + (unsigned)k16 * 32 + (unsigned)((lane >> 3) & 1) * 16;
                    ldm_x4(bf[2*nt2][0], bf[2*nt2][1], bf[2*nt2+1][0], bf[2*nt2+1][1], addr);
                }
#pragma unroll
                for (int nt = 0; nt < 8; nt++)
                    mma_f16(accs[nt], qa[k16], bf[nt]);
            }

            // ---- scale + causal mask + row max ----
            float mx0 = m_r[0], mx1 = m_r[1];
#pragma unroll
            for (int nt = 0; nt < 8; nt++) {
                const int colb = k0 + 8*nt + 2*c;
                float v0 = accs[nt][0] * SCALE; if (colb     > qi0) v0 = -1e30f;
                float v1 = accs[nt][1] * SCALE; if (colb + 1 > qi0) v1 = -1e30f;
                float v2 = accs[nt][2] * SCALE; if (colb     > qi1) v2 = -1e30f;
                float v3 = accs[nt][3] * SCALE; if (colb + 1 > qi1) v3 = -1e30f;
                accs[nt][0] = v0; accs[nt][1] = v1; accs[nt][2] = v2; accs[nt][3] = v3;
                mx0 = fmaxf(mx0, fmaxf(v0, v1));
                mx1 = fmaxf(mx1, fmaxf(v2, v3));
            }
            mx0 = fmaxf(mx0, __shfl_xor_sync(0xffffffffu, mx0, 1));
            mx0 = fmaxf(mx0, __shfl_xor_sync(0xffffffffu, mx0, 2));
            mx1 = fmaxf(mx1, __shfl_xor_sync(0xffffffffu, mx1, 1));
            mx1 = fmaxf(mx1, __shfl_xor_sync(0xffffffffu, mx1, 2));

            const float alpha0 = __expf(m_r[0] - mx0);
            const float alpha1 = __expf(m_r[1] - mx1);
            m_r[0] = mx0; m_r[1] = mx1;

            // ---- exp; round P to fp16; l sums the ROUNDED p ----
            float ls0 = 0.f, ls1 = 0.f;
#pragma unroll
            for (int nt = 0; nt < 8; nt++) {
                __half2 p01 = __floats2half2_rn(__expf(accs[nt][0] - mx0),
                                                __expf(accs[nt][1] - mx0));
                __half2 p23 = __floats2half2_rn(__expf(accs[nt][2] - mx1),
                                                __expf(accs[nt][3] - mx1));
                float2 f01 = __half22float2(p01);
                float2 f23 = __half22float2(p23);
                ls0 += f01.x + f01.y;
                ls1 += f23.x + f23.y;
                *(__half2*)&sP[(wm + g    )*APSTR + 8*nt + 2*c] = p01;
                *(__half2*)&sP[(wm + g + 8)*APSTR + 8*nt + 2*c] = p23;
            }
            ls0 += __shfl_xor_sync(0xffffffffu, ls0, 1);
            ls0 += __shfl_xor_sync(0xffffffffu, ls0, 2);
            ls1 += __shfl_xor_sync(0xffffffffu, ls1, 1);
            ls1 += __shfl_xor_sync(0xffffffffu, ls1, 2);
            l_r[0] = l_r[0] * alpha0 + ls0;
            l_r[1] = l_r[1] * alpha1 + ls1;

#pragma unroll
            for (int nt = 0; nt < 16; nt++) {
                acco[nt][0] *= alpha0; acco[nt][1] *= alpha0;
                acco[nt][2] *= alpha1; acco[nt][3] *= alpha1;
            }
            __syncwarp();   // sP rows are warp-private

            // ---- O += P V ----
#pragma unroll
            for (int k16 = 0; k16 < 4; k16++) {
                unsigned a[4];
                {
                    const unsigned addr = uP + (unsigned)(wm + (lane & 15)) * (APSTR*2)
                                        + (unsigned)k16 * 32 + ((unsigned)(lane >> 4) << 4);
                    ldm_x4(a[0], a[1], a[2], a[3], addr);
                }
#pragma unroll
                for (int nt2 = 0; nt2 < 8; nt2++) {
                    unsigned bf[2][2];
                    const unsigned addr = uV
                        + (unsigned)(k16*16 + (lane & 7) + (((lane >> 3) & 1) << 3)) * (AQSTR*2)
                        + (unsigned)(2*nt2 + (lane >> 4)) * 16;
                    ldm_x4_t(bf[0][0], bf[0][1], bf[1][0], bf[1][1], addr);
                    mma_f16(acco[2*nt2],     a, bf[0]);
                    mma_f16(acco[2*nt2 + 1], a, bf[1]);
                }
            }
        }

        // Epilogue: normalize, write fp16 [B*S, H]
        const float inv0 = 1.f / l_r[0];
        const float inv1 = 1.f / l_r[1];
        __half* base0 = out + ((size_t)(b*SEQ + q0 + wm + g    ))*HID + h*HD;
        __half* base1 = out + ((size_t)(b*SEQ + q0 + wm + g + 8))*HID + h*HD;
#pragma unroll
        for (int nt = 0; nt < 16; nt++) {
            *(__half2*)&base0[8*nt + 2*c] =
                __floats2half2_rn(acco[nt][0]*inv0, acco[nt][1]*inv0);
            *(__half2*)&base1[8*nt + 2*c] =
                __floats2half2_rn(acco[nt][2]*inv1, acco[nt][3]*inv1);
        }
    }
}

// ---------------------------------------------------------------------------
// Launch
// ---------------------------------------------------------------------------
extern "C" void kernel_launch(void* const* d_in, const int* in_sizes, int n_in,
                              void* d_out, int out_size)
{
    const float* x  = (const float*)d_in[0];

    __half *qh, *kh, *vh, *xh, *wh;
    float *tS, *tC;
    cudaGetSymbolAddress((void**)&qh, g_Qh);
    cudaGetSymbolAddress((void**)&kh, g_Kh);
    cudaGetSymbolAddress((void**)&vh, g_Vh);
    cudaGetSymbolAddress((void**)&xh, g_xh);
    cudaGetSymbolAddress((void**)&wh, g_wh);
    cudaGetSymbolAddress((void**)&tS, g_tS);
    cudaGetSymbolAddress((void**)&tC, g_tC);

    const size_t wstride = (size_t)HID*HID;

    // Fused prep: x cvt + 4 weight cvts + rope tables, one launch
    prep_kernel<<<PREP_GRID, 256>>>(x,
        (const float*)d_in[1], (const float*)d_in[2],
        (const float*)d_in[3], (const float*)d_in[4],
        xh, wh, tS, tC);

    cudaFuncSetAttribute(gemm_fp16_kernel, cudaFuncAttributeMaxDynamicSharedMemorySize,
                         G_SMEM);

    // Fused QKV projection + rope epilogue: writes qh/kh/vh fp16 directly
    gemm_fp16_kernel<<<dim3(3*HID/128, MTOT/128), 256, G_SMEM>>>(
        xh, wh, qh, kh, vh, nullptr, tS, tC, 0);

    cudaFuncSetAttribute(attn_f16_kernel, cudaFuncAttributeMaxDynamicSharedMemorySize,
                         ATTN_SMEM);
    // attn writes fp16 output into xh (x no longer needed); paired q-tiles
    attn_f16_kernel<<<dim3(NBX/2, BATCH*NHEAD), 256, ATTN_SMEM>>>(qh, kh, vh, xh);

    // O projection (fp32 row-major to d_out)
    gemm_fp16_kernel<<<dim3(HID/128, MTOT/128), 256, G_SMEM>>>(
        xh, wh + 3*wstride, nullptr, nullptr, nullptr, (float*)d_out,
        nullptr, nullptr, 1);
}